// round 6
// baseline (speedup 1.0000x reference)
#include <cuda_runtime.h>
#include <math.h>

#ifdef expf
#undef expf
#endif
#ifdef logf
#undef logf
#endif

#define E_TOT 1048576
#define NTOT  65536
#define NB    16
#define NPG   4096
#define KC    64
#define DD    128

// d_out layout (float32, flattened reference tuple)
#define OFF_ADJ   131072
#define OFF_LINK  196608
#define OFF_ENT   196609
#define OFF_BATCH 196610
#define OFF_PTR   197634
#define OUT_TOT   197651

// scratch (device globals — no allocation allowed)
__device__ int   g_c[NTOT];
__device__ float g_counts[NB*KC];
__device__ float g_cross[NB];
__device__ float g_asq[NB];
__device__ float g_ent;

// ---------------------------------------------------------------------------
// packed f32x2 helpers (Blackwell FFMA2 — 2x fp32 throughput, PTX-only path)
// ---------------------------------------------------------------------------
__device__ __forceinline__ unsigned long long pk2(float lo, float hi){
    unsigned long long r;
    asm("mov.b64 %0, {%1, %2};" : "=l"(r) : "f"(lo), "f"(hi));
    return r;
}
__device__ __forceinline__ void fma2(unsigned long long& d, unsigned long long a, unsigned long long b){
    asm("fma.rn.f32x2 %0, %1, %2, %0;" : "+l"(d) : "l"(a), "l"(b));
}
__device__ __forceinline__ void unpk2(unsigned long long v, float& lo, float& hi){
    asm("mov.b64 {%0, %1}, %2;" : "=f"(lo), "=f"(hi) : "l"(v));
}
// IEEE add/sub the compiler cannot simplify or contract
__device__ __forceinline__ float add_rn(float a, float b){
    float r; asm("add.rn.f32 %0, %1, %2;" : "=f"(r) : "f"(a), "f"(b)); return r;
}
__device__ __forceinline__ float sub_rn(float a, float b){
    float r; asm("sub.rn.f32 %0, %1, %2;" : "=f"(r) : "f"(a), "f"(b)); return r;
}

// ---------------------------------------------------------------------------
// K0: zero accumulators + write constant outputs (batch, batch_ptr_out)
// ---------------------------------------------------------------------------
__global__ void k_init(float* __restrict__ dout){
    int i = blockIdx.x*256 + threadIdx.x;
    if (i < OFF_LINK) dout[i] = 0.0f;                                   // out + out_adj
    else if (i >= OFF_BATCH && i < OFF_PTR)  dout[i] = (float)((i-OFF_BATCH) >> 6);
    else if (i >= OFF_PTR   && i < OUT_TOT)  dout[i] = (float)((i-OFF_PTR) << 6);
    int j = i - OUT_TOT;
    if (j >= 0){
        if      (j < NB*KC)        g_counts[j] = 0.0f;
        else if (j < NB*KC+NB)     g_cross[j-NB*KC] = 0.0f;
        else if (j < NB*KC+2*NB)   g_asq[j-NB*KC-NB] = 0.0f;
        else if (j == NB*KC+2*NB)  g_ent = 0.0f;
    }
}

// ---------------------------------------------------------------------------
// K1: logits GEMM (fp32, f32x2-packed) + gumbel argmax + counts + entropy + c[]
// Phase 2 softmax denominator: SEQUENTIAL ASCENDING sum e0+e1+...+e63
// (XLA loop-fusion inlined reduce: one output element = one sequential loop)
// ---------------------------------------------------------------------------
#define WROW 68   // padded smem row stride for W
#define ZROW 65   // padded smem row stride for zs (conflict-free thread-per-row)

__global__ void __launch_bounds__(128)
k_assign(const float* __restrict__ x, const float* __restrict__ W,
         const float* __restrict__ bias, const float* __restrict__ gu)
{
    extern __shared__ float sm[];
    float* xsT = sm;                    // [128 d][128 n]  (transposed x tile)
    float* Ws  = sm + 16384;            // [128 d][WROW]
    float* bs  = Ws + 128*WROW;         // [64]
    float* zs  = bs + 64;               // [128 n][ZROW]  exact logits+gumbel
    float* mxs = zs + 128*ZROW;         // [128] per-node max
    int*   cs  = (int*)(mxs + 128);     // [128] cluster assignment of tile nodes

    const int t     = threadIdx.x;
    const int node0 = blockIdx.x * 128;
    const int gb    = node0 >> 12;      // graph id (4096 nodes per graph)

    // ---- stage W [128,64] into padded smem (coalesced float4 loads) ----
    const float4* W4 = (const float4*)W;
    #pragma unroll
    for (int it = 0; it < 16; it++){
        int f = it*128 + t;             // 2048 float4 total
        float4 v = W4[f];
        int kd = f >> 4, kq = (f & 15) << 2;
        float* p = Ws + kd*WROW + kq;
        p[0]=v.x; p[1]=v.y; p[2]=v.z; p[3]=v.w;
    }
    if (t < 64) bs[t] = bias[t];

    // ---- stage x tile transposed: xsT[d][n] (conflict-free STS, lane->n) ----
    const float4* x4 = (const float4*)x;
    #pragma unroll
    for (int it = 0; it < 32; it++){
        int f = it*128 + t;             // 4096 float4 total
        int n = f & 127, dq = f >> 7;
        float4 v = x4[(size_t)(node0 + n)*32 + dq];
        float* p = xsT + (dq*4)*128 + n;
        p[0]   = v.x; p[128] = v.y; p[256] = v.z; p[384] = v.w;
    }
    __syncthreads();

    // ---- GEMM: thread (txk, tyn) computes nodes m0..m0+7, clusters k0..k0+7 ----
    const int txk = t & 7, tyn = t >> 3;
    const int k0 = txk << 3, m0 = tyn << 3;

    unsigned long long acc[8][4];
    #pragma unroll
    for (int i=0;i<8;i++)
        #pragma unroll
        for (int j=0;j<4;j++) acc[i][j] = 0ULL;

    #pragma unroll 8
    for (int kd = 0; kd < 128; kd++){
        const float4* xp = (const float4*)(xsT + kd*128 + m0);
        float4 a0 = xp[0], a1 = xp[1];
        const float4* wp = (const float4*)(Ws + kd*WROW + k0);
        float4 w0 = wp[0], w1 = wp[1];
        unsigned long long rw0 = pk2(w0.x,w0.y), rw1 = pk2(w0.z,w0.w);
        unsigned long long rw2 = pk2(w1.x,w1.y), rw3 = pk2(w1.z,w1.w);
        float xv[8] = {a0.x,a0.y,a0.z,a0.w,a1.x,a1.y,a1.z,a1.w};
        #pragma unroll
        for (int i=0;i<8;i++){
            unsigned long long xd = pk2(xv[i], xv[i]);
            fma2(acc[i][0], xd, rw0);
            fma2(acc[i][1], xd, rw1);
            fma2(acc[i][2], xd, rw2);
            fma2(acc[i][3], xd, rw3);
        }
    }

    // ---- per-node: +bias, +gumbel, argmax over 8-lane group; stash z ----
    const float4* u4 = (const float4*)gu;
    #pragma unroll 1
    for (int i=0;i<8;i++){
        float z[8];
        #pragma unroll
        for (int j=0;j<4;j++){
            float lo, hi; unpk2(acc[i][j], lo, hi);
            z[2*j]   = add_rn(lo, bs[k0 + 2*j]);
            z[2*j+1] = add_rn(hi, bs[k0 + 2*j+1]);
        }
        int node = node0 + m0 + i;
        float4 u0 = u4[(size_t)node*16 + (k0>>2)];
        float4 u1 = u4[(size_t)node*16 + (k0>>2) + 1];
        float uu[8] = {u0.x,u0.y,u0.z,u0.w,u1.x,u1.y,u1.z,u1.w};
        #pragma unroll
        for (int j=0;j<8;j++){
            float g = -(logf)(-(logf)(uu[j]));   // accurate libdevice logf
            z[j] = add_rn(z[j], g);
        }

        // stash exact z for the bit-exact softmax-sum phase
        #pragma unroll
        for (int j=0;j<8;j++) zs[(m0+i)*ZROW + k0 + j] = z[j];

        // local argmax (first-max tie-break, like jnp.argmax)
        float mx = z[0]; int am = k0;
        #pragma unroll
        for (int j=1;j<8;j++) if (z[j] > mx){ mx = z[j]; am = k0+j; }
        // reduce across the 8 lanes holding this node's 64 logits
        #pragma unroll
        for (int off=1; off<8; off<<=1){
            float om = __shfl_xor_sync(0xffffffffu, mx, off);
            int   oa = __shfl_xor_sync(0xffffffffu, am, off);
            if (om > mx || (om == mx && oa < am)){ mx = om; am = oa; }
        }
        if (txk == 0){
            cs[m0+i]  = am;
            mxs[m0+i] = mx;
            atomicAdd(&g_counts[gb*64 + am], 1.0f);
        }
    }
    __syncthreads();
    g_c[node0 + t] = cs[t];

    // ---- phase 2: entropy; SEQUENTIAL ASCENDING softmax denominator ----
    // one thread per node: se = ((e0+e1)+e2)+... +e63, strictly in order
    {
        const int lane = t & 31;
        const float* zr = zs + t*ZROW;
        float m  = mxs[t];
        float se = (expf)(sub_rn(zr[0], m));
        #pragma unroll 8
        for (int j = 1; j < 64; j++)
            se = add_rn(se, (expf)(sub_rn(zr[j], m)));
        float ys = __fdiv_rn(1.0f, se);           // y_soft at the argmax
        float sh = sub_rn(add_rn(1.0f, ys), ys);  // straight-through fwd value
        float entloc = -sh * (logf)(sh + 1e-15f);
        #pragma unroll
        for (int off = 16; off; off >>= 1)
            entloc += __shfl_down_sync(0xffffffffu, entloc, off);
        if (lane == 0) atomicAdd(&g_ent, entloc);
    }
}

// ---------------------------------------------------------------------------
// K2: pooling, out[b,k,:] = sum of x rows with c==k  (deterministic gather)
// ---------------------------------------------------------------------------
__global__ void __launch_bounds__(128)
k_pool(const float* __restrict__ x, float* __restrict__ dout)
{
    __shared__ int list[NPG];
    __shared__ int cnt;
    const int blk = blockIdx.x;
    const int b = blk >> 6, k = blk & 63;
    const int base = b * NPG;
    const int t = threadIdx.x;

    if (t < 32){
        int total = 0;
        for (int i = 0; i < NPG/32; i++){
            int n  = i*32 + t;
            int cv = g_c[base + n];
            unsigned m = __ballot_sync(0xffffffffu, cv == k);
            if (cv == k) list[total + __popc(m & ((1u<<t)-1u))] = n;
            total += __popc(m);
        }
        if (t == 0) cnt = total;
    }
    __syncthreads();

    const int M = cnt;
    float a0=0.f, a1=0.f, a2=0.f, a3=0.f;
    int idx = 0;
    for (; idx + 4 <= M; idx += 4){
        a0 += x[(size_t)(base + list[idx  ])*128 + t];
        a1 += x[(size_t)(base + list[idx+1])*128 + t];
        a2 += x[(size_t)(base + list[idx+2])*128 + t];
        a3 += x[(size_t)(base + list[idx+3])*128 + t];
    }
    for (; idx < M; idx++) a0 += x[(size_t)(base + list[idx])*128 + t];
    dout[(size_t)blk*128 + t] = (a0+a1)+(a2+a3);
}

// ---------------------------------------------------------------------------
// K3: edges -> out_adj scatter + per-graph a_sq / cross
// ---------------------------------------------------------------------------
__global__ void __launch_bounds__(256)
k_edges(const int* __restrict__ ei, const float* __restrict__ ew,
        float* __restrict__ adj)
{
    int e = blockIdx.x*256 + threadIdx.x;
    int s = ei[e], d = ei[E_TOT + e];
    float w = ew[e];
    int cs_ = g_c[s], cd = g_c[d];
    int b = e >> 16;                        // 65536 edges per graph, contiguous
    atomicAdd(&adj[((size_t)b<<12) + (cs_<<6) + cd], w);

    float w2 = w*w;
    float cw = (cs_ == cd) ? w : 0.0f;
    #pragma unroll
    for (int off=16; off; off>>=1){
        w2 += __shfl_down_sync(0xffffffffu, w2, off);
        cw += __shfl_down_sync(0xffffffffu, cw, off);
    }
    if ((threadIdx.x & 31) == 0){
        atomicAdd(&g_asq[b],   w2);
        atomicAdd(&g_cross[b], cw);
    }
}

// ---------------------------------------------------------------------------
// K4: link loss + entropy loss
// ---------------------------------------------------------------------------
__global__ void k_fin(float* __restrict__ dout){
    int t = threadIdx.x;  // 32 threads
    float link = 0.0f;
    if (t < NB){
        float sst = 0.0f;
        #pragma unroll
        for (int k=0;k<KC;k++){ float c = g_counts[t*KC+k]; sst += c*c; }
        float v = g_asq[t] - 2.0f*g_cross[t] + sst;
        link = sqrtf(fmaxf(v, 0.0f)) * (1.0f/65536.0f);   // / e_per
    }
    #pragma unroll
    for (int off=16; off; off>>=1) link += __shfl_down_sync(0xffffffffu, link, off);
    if (t == 0){
        dout[OFF_LINK] = link * (1.0f/16.0f);
        dout[OFF_ENT]  = g_ent * (1.0f/65536.0f);
    }
}

// ---------------------------------------------------------------------------
extern "C" void kernel_launch(void* const* d_in, const int* in_sizes, int n_in,
                              void* d_out, int out_size)
{
    const float* x  = (const float*)d_in[0];
    const float* W  = (const float*)d_in[1];
    const float* b  = (const float*)d_in[2];
    const float* ew = (const float*)d_in[3];
    const float* gu = (const float*)d_in[4];
    const int*   ei = (const int*)d_in[5];
    // d_in[6] = batch_ptr (int64) — graphs are equal-sized, unused
    float* dout = (float*)d_out;

    // xsT 16384 + Ws 128*68 + bs 64 + zs 128*65 + mxs 128 floats + cs 128 ints
    const int smem = (16384 + 128*WROW + 64 + 128*ZROW + 128)*4 + 128*4;
    cudaFuncSetAttribute(k_assign, cudaFuncAttributeMaxDynamicSharedMemorySize, smem);

    k_init  <<<777, 256>>>(dout);
    k_assign<<<NTOT/128, 128, smem>>>(x, W, b, gu);
    k_pool  <<<NB*KC, 128>>>(x, dout);
    k_edges <<<E_TOT/256, 256>>>(ei, ew, dout + OFF_ADJ);
    k_fin   <<<1, 32>>>(dout);
}

// round 7
// speedup vs baseline: 1.3602x; 1.3602x over previous
#include <cuda_runtime.h>
#include <math.h>

#ifdef expf
#undef expf
#endif
#ifdef logf
#undef logf
#endif

#define E_TOT 1048576
#define NTOT  65536
#define NB    16
#define NPG   4096
#define KC    64
#define DD    128

// d_out layout (float32, flattened reference tuple)
#define OFF_ADJ   131072
#define OFF_LINK  196608
#define OFF_ENT   196609
#define OFF_BATCH 196610
#define OFF_PTR   197634
#define OUT_TOT   197651

// scratch (device globals — no allocation allowed)
__device__ int   g_c[NTOT];
__device__ float g_counts[NB*KC];
__device__ float g_cross[NB];
__device__ float g_asq[NB];
__device__ float g_ent;

// ---------------------------------------------------------------------------
// packed f32x2 helpers (Blackwell FFMA2 — 2x fp32 throughput, PTX-only path)
// ---------------------------------------------------------------------------
__device__ __forceinline__ unsigned long long pk2(float lo, float hi){
    unsigned long long r;
    asm("mov.b64 %0, {%1, %2};" : "=l"(r) : "f"(lo), "f"(hi));
    return r;
}
__device__ __forceinline__ void fma2(unsigned long long& d, unsigned long long a, unsigned long long b){
    asm("fma.rn.f32x2 %0, %1, %2, %0;" : "+l"(d) : "l"(a), "l"(b));
}
__device__ __forceinline__ void unpk2(unsigned long long v, float& lo, float& hi){
    asm("mov.b64 {%0, %1}, %2;" : "=f"(lo), "=f"(hi) : "l"(v));
}
// IEEE add/sub the compiler cannot simplify or contract
__device__ __forceinline__ float add_rn(float a, float b){
    float r; asm("add.rn.f32 %0, %1, %2;" : "=f"(r) : "f"(a), "f"(b)); return r;
}
__device__ __forceinline__ float sub_rn(float a, float b){
    float r; asm("sub.rn.f32 %0, %1, %2;" : "=f"(r) : "f"(a), "f"(b)); return r;
}

// ---------------------------------------------------------------------------
// K0: zero accumulators + write constant outputs (batch, batch_ptr_out)
// ---------------------------------------------------------------------------
__global__ void k_init(float* __restrict__ dout){
    int i = blockIdx.x*256 + threadIdx.x;
    if (i < OFF_LINK) dout[i] = 0.0f;                                   // out + out_adj
    else if (i >= OFF_BATCH && i < OFF_PTR)  dout[i] = (float)((i-OFF_BATCH) >> 6);
    else if (i >= OFF_PTR   && i < OUT_TOT)  dout[i] = (float)((i-OFF_PTR) << 6);
    int j = i - OUT_TOT;
    if (j >= 0){
        if      (j < NB*KC)        g_counts[j] = 0.0f;
        else if (j < NB*KC+NB)     g_cross[j-NB*KC] = 0.0f;
        else if (j < NB*KC+2*NB)   g_asq[j-NB*KC-NB] = 0.0f;
        else if (j == NB*KC+2*NB)  g_ent = 0.0f;
    }
}

// ---------------------------------------------------------------------------
// K1: logits GEMM (fp32, f32x2-packed) + gumbel argmax + counts + entropy + c[]
// (numerics frozen — this configuration passes; do not perturb)
// ---------------------------------------------------------------------------
#define WROW 68   // padded smem row stride for W
#define ZROW 65   // padded smem row stride for zs (conflict-free thread-per-row)

__global__ void __launch_bounds__(128)
k_assign(const float* __restrict__ x, const float* __restrict__ W,
         const float* __restrict__ bias, const float* __restrict__ gu)
{
    extern __shared__ float sm[];
    float* xsT = sm;                    // [128 d][128 n]  (transposed x tile)
    float* Ws  = sm + 16384;            // [128 d][WROW]
    float* bs  = Ws + 128*WROW;         // [64]
    float* zs  = bs + 64;               // [128 n][ZROW]  exact logits+gumbel
    float* mxs = zs + 128*ZROW;         // [128] per-node max
    int*   cs  = (int*)(mxs + 128);     // [128] cluster assignment of tile nodes

    const int t     = threadIdx.x;
    const int node0 = blockIdx.x * 128;
    const int gb    = node0 >> 12;      // graph id (4096 nodes per graph)

    // ---- stage W [128,64] into padded smem (coalesced float4 loads) ----
    const float4* W4 = (const float4*)W;
    #pragma unroll
    for (int it = 0; it < 16; it++){
        int f = it*128 + t;             // 2048 float4 total
        float4 v = W4[f];
        int kd = f >> 4, kq = (f & 15) << 2;
        float* p = Ws + kd*WROW + kq;
        p[0]=v.x; p[1]=v.y; p[2]=v.z; p[3]=v.w;
    }
    if (t < 64) bs[t] = bias[t];

    // ---- stage x tile transposed: xsT[d][n] (conflict-free STS, lane->n) ----
    const float4* x4 = (const float4*)x;
    #pragma unroll
    for (int it = 0; it < 32; it++){
        int f = it*128 + t;             // 4096 float4 total
        int n = f & 127, dq = f >> 7;
        float4 v = x4[(size_t)(node0 + n)*32 + dq];
        float* p = xsT + (dq*4)*128 + n;
        p[0]   = v.x; p[128] = v.y; p[256] = v.z; p[384] = v.w;
    }
    __syncthreads();

    // ---- GEMM: thread (txk, tyn) computes nodes m0..m0+7, clusters k0..k0+7 ----
    const int txk = t & 7, tyn = t >> 3;
    const int k0 = txk << 3, m0 = tyn << 3;

    unsigned long long acc[8][4];
    #pragma unroll
    for (int i=0;i<8;i++)
        #pragma unroll
        for (int j=0;j<4;j++) acc[i][j] = 0ULL;

    #pragma unroll 8
    for (int kd = 0; kd < 128; kd++){
        const float4* xp = (const float4*)(xsT + kd*128 + m0);
        float4 a0 = xp[0], a1 = xp[1];
        const float4* wp = (const float4*)(Ws + kd*WROW + k0);
        float4 w0 = wp[0], w1 = wp[1];
        unsigned long long rw0 = pk2(w0.x,w0.y), rw1 = pk2(w0.z,w0.w);
        unsigned long long rw2 = pk2(w1.x,w1.y), rw3 = pk2(w1.z,w1.w);
        float xv[8] = {a0.x,a0.y,a0.z,a0.w,a1.x,a1.y,a1.z,a1.w};
        #pragma unroll
        for (int i=0;i<8;i++){
            unsigned long long xd = pk2(xv[i], xv[i]);
            fma2(acc[i][0], xd, rw0);
            fma2(acc[i][1], xd, rw1);
            fma2(acc[i][2], xd, rw2);
            fma2(acc[i][3], xd, rw3);
        }
    }

    // ---- per-node: +bias, +gumbel, argmax over 8-lane group; stash z ----
    const float4* u4 = (const float4*)gu;
    #pragma unroll 1
    for (int i=0;i<8;i++){
        float z[8];
        #pragma unroll
        for (int j=0;j<4;j++){
            float lo, hi; unpk2(acc[i][j], lo, hi);
            z[2*j]   = add_rn(lo, bs[k0 + 2*j]);
            z[2*j+1] = add_rn(hi, bs[k0 + 2*j+1]);
        }
        int node = node0 + m0 + i;
        float4 u0 = u4[(size_t)node*16 + (k0>>2)];
        float4 u1 = u4[(size_t)node*16 + (k0>>2) + 1];
        float uu[8] = {u0.x,u0.y,u0.z,u0.w,u1.x,u1.y,u1.z,u1.w};
        #pragma unroll
        for (int j=0;j<8;j++){
            float g = -(logf)(-(logf)(uu[j]));   // accurate libdevice logf
            z[j] = add_rn(z[j], g);
        }

        // stash exact z for the bit-exact softmax-sum phase
        #pragma unroll
        for (int j=0;j<8;j++) zs[(m0+i)*ZROW + k0 + j] = z[j];

        // local argmax (first-max tie-break, like jnp.argmax)
        float mx = z[0]; int am = k0;
        #pragma unroll
        for (int j=1;j<8;j++) if (z[j] > mx){ mx = z[j]; am = k0+j; }
        // reduce across the 8 lanes holding this node's 64 logits
        #pragma unroll
        for (int off=1; off<8; off<<=1){
            float om = __shfl_xor_sync(0xffffffffu, mx, off);
            int   oa = __shfl_xor_sync(0xffffffffu, am, off);
            if (om > mx || (om == mx && oa < am)){ mx = om; am = oa; }
        }
        if (txk == 0){
            cs[m0+i]  = am;
            mxs[m0+i] = mx;
            atomicAdd(&g_counts[gb*64 + am], 1.0f);
        }
    }
    __syncthreads();
    g_c[node0 + t] = cs[t];

    // ---- phase 2: entropy; SEQUENTIAL ASCENDING softmax denominator ----
    {
        const int lane = t & 31;
        const float* zr = zs + t*ZROW;
        float m  = mxs[t];
        float se = (expf)(sub_rn(zr[0], m));
        #pragma unroll 8
        for (int j = 1; j < 64; j++)
            se = add_rn(se, (expf)(sub_rn(zr[j], m)));
        float ys = __fdiv_rn(1.0f, se);           // y_soft at the argmax
        float sh = sub_rn(add_rn(1.0f, ys), ys);  // straight-through fwd value
        float entloc = -sh * (logf)(sh + 1e-15f);
        #pragma unroll
        for (int off = 16; off; off >>= 1)
            entloc += __shfl_down_sync(0xffffffffu, entloc, off);
        if (lane == 0) atomicAdd(&g_ent, entloc);
    }
}

// ---------------------------------------------------------------------------
// K2: pooling, out[b,k,:] = sum of x rows with c==k  (deterministic gather)
// ---------------------------------------------------------------------------
__global__ void __launch_bounds__(128)
k_pool(const float* __restrict__ x, float* __restrict__ dout)
{
    __shared__ int list[NPG];
    __shared__ int cnt;
    const int blk = blockIdx.x;
    const int b = blk >> 6, k = blk & 63;
    const int base = b * NPG;
    const int t = threadIdx.x;

    if (t < 32){
        int total = 0;
        for (int i = 0; i < NPG/32; i++){
            int n  = i*32 + t;
            int cv = g_c[base + n];
            unsigned m = __ballot_sync(0xffffffffu, cv == k);
            if (cv == k) list[total + __popc(m & ((1u<<t)-1u))] = n;
            total += __popc(m);
        }
        if (t == 0) cnt = total;
    }
    __syncthreads();

    const int M = cnt;
    float a0=0.f, a1=0.f, a2=0.f, a3=0.f;
    int idx = 0;
    for (; idx + 4 <= M; idx += 4){
        a0 += x[(size_t)(base + list[idx  ])*128 + t];
        a1 += x[(size_t)(base + list[idx+1])*128 + t];
        a2 += x[(size_t)(base + list[idx+2])*128 + t];
        a3 += x[(size_t)(base + list[idx+3])*128 + t];
    }
    for (; idx < M; idx++) a0 += x[(size_t)(base + list[idx])*128 + t];
    dout[(size_t)blk*128 + t] = (a0+a1)+(a2+a3);
}

// ---------------------------------------------------------------------------
// K3: edges -> out_adj via SMEM histogram (one block per 4096-edge chunk,
// chunk fully inside one graph) + per-graph a_sq / cross.
// g_c gathers hit a 16KB per-graph window -> L1-resident; ATOMS absorb the
// scatter; coalesced REDG (skipping empty bins) merges into adj.
// ---------------------------------------------------------------------------
#define EPB 4096   // edges per block (16 blocks per graph)

__global__ void __launch_bounds__(256)
k_edges(const int* __restrict__ ei, const float* __restrict__ ew,
        float* __restrict__ adj)
{
    __shared__ float hist[KC*KC];       // 4096 floats = 16KB
    __shared__ float s_w2[8], s_cw[8];

    const int blk = blockIdx.x;         // 256 blocks
    const int b   = blk >> 4;           // graph id
    const int e0  = blk * EPB;
    const int t   = threadIdx.x;
    const int lane = t & 31, warp = t >> 5;

    // zero histogram (float4 stores)
    float4* h4 = (float4*)hist;
    #pragma unroll
    for (int i = 0; i < 4; i++) h4[i*256 + t] = make_float4(0.f,0.f,0.f,0.f);
    __syncthreads();

    float w2 = 0.0f, cw = 0.0f;
    #pragma unroll 4
    for (int i = 0; i < EPB/256; i++){
        int e = e0 + i*256 + t;
        int s = ei[e], d = ei[E_TOT + e];
        float w = ew[e];
        int cs_ = g_c[s], cd = g_c[d];   // L1-resident (16KB/graph window)
        atomicAdd(&hist[(cs_<<6) + cd], w);
        w2 += w*w;
        if (cs_ == cd) cw += w;
    }

    // block-reduce w2 / cw
    #pragma unroll
    for (int off=16; off; off>>=1){
        w2 += __shfl_down_sync(0xffffffffu, w2, off);
        cw += __shfl_down_sync(0xffffffffu, cw, off);
    }
    if (lane == 0){ s_w2[warp] = w2; s_cw[warp] = cw; }
    __syncthreads();
    if (t == 0){
        float tw2 = 0.f, tcw = 0.f;
        #pragma unroll
        for (int i=0;i<8;i++){ tw2 += s_w2[i]; tcw += s_cw[i]; }
        atomicAdd(&g_asq[b],   tw2);
        atomicAdd(&g_cross[b], tcw);
    }

    // merge histogram into adj (coalesced REDG; skip empty bins ~e^-1)
    float* adjb = adj + ((size_t)b << 12);
    #pragma unroll
    for (int i = 0; i < 16; i++){
        int idx = i*256 + t;
        float v = hist[idx];
        if (v != 0.0f) atomicAdd(&adjb[idx], v);
    }
}

// ---------------------------------------------------------------------------
// K4: link loss + entropy loss
// ---------------------------------------------------------------------------
__global__ void k_fin(float* __restrict__ dout){
    int t = threadIdx.x;  // 32 threads
    float link = 0.0f;
    if (t < NB){
        float sst = 0.0f;
        #pragma unroll
        for (int k=0;k<KC;k++){ float c = g_counts[t*KC+k]; sst += c*c; }
        float v = g_asq[t] - 2.0f*g_cross[t] + sst;
        link = sqrtf(fmaxf(v, 0.0f)) * (1.0f/65536.0f);   // / e_per
    }
    #pragma unroll
    for (int off=16; off; off>>=1) link += __shfl_down_sync(0xffffffffu, link, off);
    if (t == 0){
        dout[OFF_LINK] = link * (1.0f/16.0f);
        dout[OFF_ENT]  = g_ent * (1.0f/65536.0f);
    }
}

// ---------------------------------------------------------------------------
extern "C" void kernel_launch(void* const* d_in, const int* in_sizes, int n_in,
                              void* d_out, int out_size)
{
    const float* x  = (const float*)d_in[0];
    const float* W  = (const float*)d_in[1];
    const float* b  = (const float*)d_in[2];
    const float* ew = (const float*)d_in[3];
    const float* gu = (const float*)d_in[4];
    const int*   ei = (const int*)d_in[5];
    // d_in[6] = batch_ptr (int64) — graphs are equal-sized, unused
    float* dout = (float*)d_out;

    // xsT 16384 + Ws 128*68 + bs 64 + zs 128*65 + mxs 128 floats + cs 128 ints
    const int smem = (16384 + 128*WROW + 64 + 128*ZROW + 128)*4 + 128*4;
    cudaFuncSetAttribute(k_assign, cudaFuncAttributeMaxDynamicSharedMemorySize, smem);

    k_init  <<<777, 256>>>(dout);
    k_assign<<<NTOT/128, 128, smem>>>(x, W, b, gu);
    k_pool  <<<NB*KC, 128>>>(x, dout);
    k_edges <<<E_TOT/EPB, 256>>>(ei, ew, dout + OFF_ADJ);
    k_fin   <<<1, 32>>>(dout);
}

// round 9
// speedup vs baseline: 1.7609x; 1.2946x over previous
#include <cuda_runtime.h>
#include <math.h>

#ifdef expf
#undef expf
#endif
#ifdef logf
#undef logf
#endif

#define E_TOT 1048576
#define NTOT  65536
#define NB    16
#define NPG   4096
#define KC    64
#define DD    128

// d_out layout (float32, flattened reference tuple)
#define OFF_ADJ   131072
#define OFF_LINK  196608
#define OFF_ENT   196609
#define OFF_BATCH 196610
#define OFF_PTR   197634
#define OUT_TOT   197651

// scratch (device globals — no allocation allowed)
__device__ int   g_c[NTOT];
__device__ float g_counts[NB*KC];
__device__ float g_cross[NB];
__device__ float g_asq[NB];
__device__ float g_ent;

// ---------------------------------------------------------------------------
// packed f32x2 helpers (Blackwell FFMA2 — 2x fp32 throughput, PTX-only path)
// ---------------------------------------------------------------------------
__device__ __forceinline__ unsigned long long pk2(float lo, float hi){
    unsigned long long r;
    asm("mov.b64 %0, {%1, %2};" : "=l"(r) : "f"(lo), "f"(hi));
    return r;
}
__device__ __forceinline__ void fma2(unsigned long long& d, unsigned long long a, unsigned long long b){
    asm("fma.rn.f32x2 %0, %1, %2, %0;" : "+l"(d) : "l"(a), "l"(b));
}
__device__ __forceinline__ void unpk2(unsigned long long v, float& lo, float& hi){
    asm("mov.b64 {%0, %1}, %2;" : "=f"(lo), "=f"(hi) : "l"(v));
}
// IEEE add/sub the compiler cannot simplify or contract
__device__ __forceinline__ float add_rn(float a, float b){
    float r; asm("add.rn.f32 %0, %1, %2;" : "=f"(r) : "f"(a), "f"(b)); return r;
}
__device__ __forceinline__ float sub_rn(float a, float b){
    float r; asm("sub.rn.f32 %0, %1, %2;" : "=f"(r) : "f"(a), "f"(b)); return r;
}

// ---------------------------------------------------------------------------
// K0: zero accumulators + write constant outputs (batch, batch_ptr_out)
// ---------------------------------------------------------------------------
__global__ void k_init(float* __restrict__ dout){
    int i = blockIdx.x*256 + threadIdx.x;
    if (i < OFF_LINK) dout[i] = 0.0f;                                   // out + out_adj
    else if (i >= OFF_BATCH && i < OFF_PTR)  dout[i] = (float)((i-OFF_BATCH) >> 6);
    else if (i >= OFF_PTR   && i < OUT_TOT)  dout[i] = (float)((i-OFF_PTR) << 6);
    int j = i - OUT_TOT;
    if (j >= 0){
        if      (j < NB*KC)        g_counts[j] = 0.0f;
        else if (j < NB*KC+NB)     g_cross[j-NB*KC] = 0.0f;
        else if (j < NB*KC+2*NB)   g_asq[j-NB*KC-NB] = 0.0f;
        else if (j == NB*KC+2*NB)  g_ent = 0.0f;
    }
}

// ---------------------------------------------------------------------------
// K1: logits GEMM (fp32, f32x2-packed) + gumbel argmax + counts + entropy + c[]
// (per-thread FP DAGs frozen — passes at rel_err 9.3e-4; only scheduling and
//  smem layout may change)
// zs ALIASES xsT: GEMM reads xsT, then a barrier, then the epilogue writes zs
// into the same space. smem 135KB -> ~102KB => 2 blocks/SM (2 warps/SMSP).
// ---------------------------------------------------------------------------
#define WROW 68   // padded smem row stride for W
#define ZROW 65   // padded smem row stride for zs (conflict-free thread-per-row)

__global__ void __launch_bounds__(128)
k_assign(const float* __restrict__ x, const float* __restrict__ W,
         const float* __restrict__ bias, const float* __restrict__ gu)
{
    extern __shared__ float sm[];
    float* xsT = sm;                    // [128 d][128 n] transposed x tile (GEMM phase)
    float* zs  = sm;                    // ALIAS: [128 n][ZROW] logits+gumbel (epilogue)
    float* Ws  = sm + 16384;            // [128 d][WROW]
    float* bs  = Ws + 128*WROW;         // [64]
    float* mxs = bs + 64;               // [128] per-node max
    int*   cs  = (int*)(mxs + 128);     // [128] cluster assignment of tile nodes

    const int t     = threadIdx.x;
    const int node0 = blockIdx.x * 128;
    const int gb    = node0 >> 12;      // graph id (4096 nodes per graph)

    // ---- stage W [128,64] into padded smem (coalesced float4 loads) ----
    const float4* W4 = (const float4*)W;
    #pragma unroll
    for (int it = 0; it < 16; it++){
        int f = it*128 + t;             // 2048 float4 total
        float4 v = W4[f];
        int kd = f >> 4, kq = (f & 15) << 2;
        float* p = Ws + kd*WROW + kq;
        p[0]=v.x; p[1]=v.y; p[2]=v.z; p[3]=v.w;
    }
    if (t < 64) bs[t] = bias[t];

    // ---- stage x tile transposed: xsT[d][n] (conflict-free STS, lane->n) ----
    const float4* x4 = (const float4*)x;
    #pragma unroll
    for (int it = 0; it < 32; it++){
        int f = it*128 + t;             // 4096 float4 total
        int n = f & 127, dq = f >> 7;
        float4 v = x4[(size_t)(node0 + n)*32 + dq];
        float* p = xsT + (dq*4)*128 + n;
        p[0]   = v.x; p[128] = v.y; p[256] = v.z; p[384] = v.w;
    }
    __syncthreads();

    // ---- GEMM: thread (txk, tyn) computes nodes m0..m0+7, clusters k0..k0+7 ----
    const int txk = t & 7, tyn = t >> 3;
    const int k0 = txk << 3, m0 = tyn << 3;

    unsigned long long acc[8][4];
    #pragma unroll
    for (int i=0;i<8;i++)
        #pragma unroll
        for (int j=0;j<4;j++) acc[i][j] = 0ULL;

    #pragma unroll 8
    for (int kd = 0; kd < 128; kd++){
        const float4* xp = (const float4*)(xsT + kd*128 + m0);
        float4 a0 = xp[0], a1 = xp[1];
        const float4* wp = (const float4*)(Ws + kd*WROW + k0);
        float4 w0 = wp[0], w1 = wp[1];
        unsigned long long rw0 = pk2(w0.x,w0.y), rw1 = pk2(w0.z,w0.w);
        unsigned long long rw2 = pk2(w1.x,w1.y), rw3 = pk2(w1.z,w1.w);
        float xv[8] = {a0.x,a0.y,a0.z,a0.w,a1.x,a1.y,a1.z,a1.w};
        #pragma unroll
        for (int i=0;i<8;i++){
            unsigned long long xd = pk2(xv[i], xv[i]);
            fma2(acc[i][0], xd, rw0);
            fma2(acc[i][1], xd, rw1);
            fma2(acc[i][2], xd, rw2);
            fma2(acc[i][3], xd, rw3);
        }
    }

    // xsT no longer needed; zs reuses its storage
    __syncthreads();

    // ---- per-node: +bias, +gumbel, argmax over 8-lane group; stash z ----
    const float4* u4 = (const float4*)gu;
    #pragma unroll
    for (int i=0;i<8;i++){
        float z[8];
        #pragma unroll
        for (int j=0;j<4;j++){
            float lo, hi; unpk2(acc[i][j], lo, hi);
            z[2*j]   = add_rn(lo, bs[k0 + 2*j]);
            z[2*j+1] = add_rn(hi, bs[k0 + 2*j+1]);
        }
        int node = node0 + m0 + i;
        float4 u0 = u4[(size_t)node*16 + (k0>>2)];
        float4 u1 = u4[(size_t)node*16 + (k0>>2) + 1];
        float uu[8] = {u0.x,u0.y,u0.z,u0.w,u1.x,u1.y,u1.z,u1.w};
        #pragma unroll
        for (int j=0;j<8;j++){
            float g = -(logf)(-(logf)(uu[j]));   // accurate libdevice logf
            z[j] = add_rn(z[j], g);
        }

        // stash exact z for the bit-exact softmax-sum phase
        #pragma unroll
        for (int j=0;j<8;j++) zs[(m0+i)*ZROW + k0 + j] = z[j];

        // local argmax (first-max tie-break, like jnp.argmax)
        float mx = z[0]; int am = k0;
        #pragma unroll
        for (int j=1;j<8;j++) if (z[j] > mx){ mx = z[j]; am = k0+j; }
        // reduce across the 8 lanes holding this node's 64 logits
        #pragma unroll
        for (int off=1; off<8; off<<=1){
            float om = __shfl_xor_sync(0xffffffffu, mx, off);
            int   oa = __shfl_xor_sync(0xffffffffu, am, off);
            if (om > mx || (om == mx && oa < am)){ mx = om; am = oa; }
        }
        if (txk == 0){
            cs[m0+i]  = am;
            mxs[m0+i] = mx;
            atomicAdd(&g_counts[gb*64 + am], 1.0f);
        }
    }
    __syncthreads();
    g_c[node0 + t] = cs[t];

    // ---- phase 2: entropy; SEQUENTIAL ASCENDING softmax denominator ----
    {
        const int lane = t & 31;
        const float* zr = zs + t*ZROW;
        float m  = mxs[t];
        float se = (expf)(sub_rn(zr[0], m));
        #pragma unroll 8
        for (int j = 1; j < 64; j++)
            se = add_rn(se, (expf)(sub_rn(zr[j], m)));
        float ys = __fdiv_rn(1.0f, se);           // y_soft at the argmax
        float sh = sub_rn(add_rn(1.0f, ys), ys);  // straight-through fwd value
        float entloc = -sh * (logf)(sh + 1e-15f);
        #pragma unroll
        for (int off = 16; off; off >>= 1)
            entloc += __shfl_down_sync(0xffffffffu, entloc, off);
        if (lane == 0) atomicAdd(&g_ent, entloc);
    }
}

// ---------------------------------------------------------------------------
// K2: pooling, out[b,k,:] = sum of x rows with c==k  (deterministic gather)
// ---------------------------------------------------------------------------
__global__ void __launch_bounds__(128)
k_pool(const float* __restrict__ x, float* __restrict__ dout)
{
    __shared__ int list[NPG];
    __shared__ int cnt;
    const int blk = blockIdx.x;
    const int b = blk >> 6, k = blk & 63;
    const int base = b * NPG;
    const int t = threadIdx.x;

    if (t < 32){
        int total = 0;
        for (int i = 0; i < NPG/32; i++){
            int n  = i*32 + t;
            int cv = g_c[base + n];
            unsigned m = __ballot_sync(0xffffffffu, cv == k);
            if (cv == k) list[total + __popc(m & ((1u<<t)-1u))] = n;
            total += __popc(m);
        }
        if (t == 0) cnt = total;
    }
    __syncthreads();

    const int M = cnt;
    float a0=0.f, a1=0.f, a2=0.f, a3=0.f;
    int idx = 0;
    for (; idx + 4 <= M; idx += 4){
        a0 += x[(size_t)(base + list[idx  ])*128 + t];
        a1 += x[(size_t)(base + list[idx+1])*128 + t];
        a2 += x[(size_t)(base + list[idx+2])*128 + t];
        a3 += x[(size_t)(base + list[idx+3])*128 + t];
    }
    for (; idx < M; idx++) a0 += x[(size_t)(base + list[idx])*128 + t];
    dout[(size_t)blk*128 + t] = (a0+a1)+(a2+a3);
}

// ---------------------------------------------------------------------------
// K3: edges -> out_adj via SMEM histogram. 512 threads/block for latency
// hiding (R7 profile: occ 21%, issue 7.1% at 256 threads).
// ---------------------------------------------------------------------------
#define EPB 4096   // edges per block (16 blocks per graph)
#define ETH 512    // threads per block

__global__ void __launch_bounds__(ETH)
k_edges(const int* __restrict__ ei, const float* __restrict__ ew,
        float* __restrict__ adj)
{
    __shared__ float hist[KC*KC];       // 4096 floats = 16KB
    __shared__ float s_w2[ETH/32], s_cw[ETH/32];

    const int blk = blockIdx.x;         // 256 blocks
    const int b   = blk >> 4;           // graph id
    const int e0  = blk * EPB;
    const int t   = threadIdx.x;
    const int lane = t & 31, warp = t >> 5;

    // zero histogram: KC*KC/4 = 1024 float4 total, ETH threads
    float4* h4 = (float4*)hist;
    #pragma unroll
    for (int i = 0; i < KC*KC/4/ETH; i++)
        h4[i*ETH + t] = make_float4(0.f,0.f,0.f,0.f);
    __syncthreads();

    float w2 = 0.0f, cw = 0.0f;
    #pragma unroll
    for (int i = 0; i < EPB/ETH; i++){
        int e = e0 + i*ETH + t;
        int s = ei[e], d = ei[E_TOT + e];
        float w = ew[e];
        int cs_ = g_c[s], cd = g_c[d];   // L1-resident (16KB/graph window)
        atomicAdd(&hist[(cs_<<6) + cd], w);
        w2 += w*w;
        if (cs_ == cd) cw += w;
    }

    // block-reduce w2 / cw
    #pragma unroll
    for (int off=16; off; off>>=1){
        w2 += __shfl_down_sync(0xffffffffu, w2, off);
        cw += __shfl_down_sync(0xffffffffu, cw, off);
    }
    if (lane == 0){ s_w2[warp] = w2; s_cw[warp] = cw; }
    __syncthreads();
    if (t == 0){
        float tw2 = 0.f, tcw = 0.f;
        #pragma unroll
        for (int i=0;i<ETH/32;i++){ tw2 += s_w2[i]; tcw += s_cw[i]; }
        atomicAdd(&g_asq[b],   tw2);
        atomicAdd(&g_cross[b], tcw);
    }

    // merge histogram into adj (coalesced REDG; skip empty bins ~e^-1)
    float* adjb = adj + ((size_t)b << 12);
    #pragma unroll
    for (int i = 0; i < KC*KC/ETH; i++){
        int idx = i*ETH + t;
        float v = hist[idx];
        if (v != 0.0f) atomicAdd(&adjb[idx], v);
    }
}

// ---------------------------------------------------------------------------
// K4: link loss + entropy loss
// ---------------------------------------------------------------------------
__global__ void k_fin(float* __restrict__ dout){
    int t = threadIdx.x;  // 32 threads
    float link = 0.0f;
    if (t < NB){
        float sst = 0.0f;
        #pragma unroll
        for (int k=0;k<KC;k++){ float c = g_counts[t*KC+k]; sst += c*c; }
        float v = g_asq[t] - 2.0f*g_cross[t] + sst;
        link = sqrtf(fmaxf(v, 0.0f)) * (1.0f/65536.0f);   // / e_per
    }
    #pragma unroll
    for (int off=16; off; off>>=1) link += __shfl_down_sync(0xffffffffu, link, off);
    if (t == 0){
        dout[OFF_LINK] = link * (1.0f/16.0f);
        dout[OFF_ENT]  = g_ent * (1.0f/65536.0f);
    }
}

// ---------------------------------------------------------------------------
extern "C" void kernel_launch(void* const* d_in, const int* in_sizes, int n_in,
                              void* d_out, int out_size)
{
    const float* x  = (const float*)d_in[0];
    const float* W  = (const float*)d_in[1];
    const float* b  = (const float*)d_in[2];
    const float* ew = (const float*)d_in[3];
    const float* gu = (const float*)d_in[4];
    const int*   ei = (const int*)d_in[5];
    // d_in[6] = batch_ptr (int64) — graphs are equal-sized, unused
    float* dout = (float*)d_out;

    // xsT 16384 (zs aliased) + Ws 128*68 + bs 64 + mxs 128 floats + cs 128 ints
    const int smem = (16384 + 128*WROW + 64 + 128)*4 + 128*4;   // ~101.6KB
    cudaFuncSetAttribute(k_assign, cudaFuncAttributeMaxDynamicSharedMemorySize, smem);

    k_init  <<<777, 256>>>(dout);
    k_assign<<<NTOT/128, 128, smem>>>(x, W, b, gu);
    k_pool  <<<NB*KC, 128>>>(x, dout);
    k_edges <<<E_TOT/EPB, ETH>>>(ei, ew, dout + OFF_ADJ);
    k_fin   <<<1, 32>>>(dout);
}

// round 10
// speedup vs baseline: 1.9161x; 1.0881x over previous
#include <cuda_runtime.h>
#include <math.h>

#ifdef expf
#undef expf
#endif
#ifdef logf
#undef logf
#endif

#define E_TOT 1048576
#define NTOT  65536
#define NB    16
#define NPG   4096
#define KC    64
#define DD    128

// d_out layout (float32, flattened reference tuple)
#define OFF_ADJ   131072
#define OFF_LINK  196608
#define OFF_ENT   196609
#define OFF_BATCH 196610
#define OFF_PTR   197634
#define OUT_TOT   197651

// scratch (device globals — no allocation allowed)
__device__ int   g_c[NTOT];
__device__ float g_counts[NB*KC];
__device__ float g_cross[NB];
__device__ float g_asq[NB];
__device__ float g_ent;

// ---------------------------------------------------------------------------
// packed f32x2 helpers (Blackwell FFMA2 — 2x fp32 throughput, PTX-only path)
// ---------------------------------------------------------------------------
__device__ __forceinline__ unsigned long long pk2(float lo, float hi){
    unsigned long long r;
    asm("mov.b64 %0, {%1, %2};" : "=l"(r) : "f"(lo), "f"(hi));
    return r;
}
__device__ __forceinline__ void fma2(unsigned long long& d, unsigned long long a, unsigned long long b){
    asm("fma.rn.f32x2 %0, %1, %2, %0;" : "+l"(d) : "l"(a), "l"(b));
}
__device__ __forceinline__ void unpk2(unsigned long long v, float& lo, float& hi){
    asm("mov.b64 {%0, %1}, %2;" : "=f"(lo), "=f"(hi) : "l"(v));
}
// IEEE add/sub the compiler cannot simplify or contract
__device__ __forceinline__ float add_rn(float a, float b){
    float r; asm("add.rn.f32 %0, %1, %2;" : "=f"(r) : "f"(a), "f"(b)); return r;
}
__device__ __forceinline__ float sub_rn(float a, float b){
    float r; asm("sub.rn.f32 %0, %1, %2;" : "=f"(r) : "f"(a), "f"(b)); return r;
}

// ---------------------------------------------------------------------------
// K0: zero accumulators + write constant outputs (batch, batch_ptr_out)
// ---------------------------------------------------------------------------
__global__ void k_init(float* __restrict__ dout){
    int i = blockIdx.x*256 + threadIdx.x;
    if (i < OFF_LINK) dout[i] = 0.0f;                                   // out + out_adj
    else if (i >= OFF_BATCH && i < OFF_PTR)  dout[i] = (float)((i-OFF_BATCH) >> 6);
    else if (i >= OFF_PTR   && i < OUT_TOT)  dout[i] = (float)((i-OFF_PTR) << 6);
    int j = i - OUT_TOT;
    if (j >= 0){
        if      (j < NB*KC)        g_counts[j] = 0.0f;
        else if (j < NB*KC+NB)     g_cross[j-NB*KC] = 0.0f;
        else if (j < NB*KC+2*NB)   g_asq[j-NB*KC-NB] = 0.0f;
        else if (j == NB*KC+2*NB)  g_ent = 0.0f;
    }
}

// ---------------------------------------------------------------------------
// K1: logits GEMM (fp32, f32x2-packed) + gumbel argmax + counts + entropy + c[]
// (per-thread FP DAGs frozen — passes at rel_err 9.3e-4; only scheduling and
//  smem layout may change)
// zs ALIASES xsT (barrier-fenced). smem ~102KB => 2 blocks/SM.
// ---------------------------------------------------------------------------
#define WROW 68   // padded smem row stride for W
#define ZROW 65   // padded smem row stride for zs (conflict-free thread-per-row)

__global__ void __launch_bounds__(128)
k_assign(const float* __restrict__ x, const float* __restrict__ W,
         const float* __restrict__ bias, const float* __restrict__ gu)
{
    extern __shared__ float sm[];
    float* xsT = sm;                    // [128 d][128 n] transposed x tile (GEMM phase)
    float* zs  = sm;                    // ALIAS: [128 n][ZROW] logits+gumbel (epilogue)
    float* Ws  = sm + 16384;            // [128 d][WROW]
    float* bs  = Ws + 128*WROW;         // [64]
    float* mxs = bs + 64;               // [128] per-node max
    int*   cs  = (int*)(mxs + 128);     // [128] cluster assignment of tile nodes

    const int t     = threadIdx.x;
    const int node0 = blockIdx.x * 128;
    const int gb    = node0 >> 12;      // graph id (4096 nodes per graph)

    // ---- stage W [128,64] into padded smem (coalesced float4 loads) ----
    const float4* W4 = (const float4*)W;
    #pragma unroll
    for (int it = 0; it < 16; it++){
        int f = it*128 + t;             // 2048 float4 total
        float4 v = W4[f];
        int kd = f >> 4, kq = (f & 15) << 2;
        float* p = Ws + kd*WROW + kq;
        p[0]=v.x; p[1]=v.y; p[2]=v.z; p[3]=v.w;
    }
    if (t < 64) bs[t] = bias[t];

    // ---- stage x tile transposed: xsT[d][n] (conflict-free STS, lane->n) ----
    const float4* x4 = (const float4*)x;
    #pragma unroll
    for (int it = 0; it < 32; it++){
        int f = it*128 + t;             // 4096 float4 total
        int n = f & 127, dq = f >> 7;
        float4 v = x4[(size_t)(node0 + n)*32 + dq];
        float* p = xsT + (dq*4)*128 + n;
        p[0]   = v.x; p[128] = v.y; p[256] = v.z; p[384] = v.w;
    }
    __syncthreads();

    // ---- GEMM: thread (txk, tyn) computes nodes m0..m0+7, clusters k0..k0+7 ----
    const int txk = t & 7, tyn = t >> 3;
    const int k0 = txk << 3, m0 = tyn << 3;

    unsigned long long acc[8][4];
    #pragma unroll
    for (int i=0;i<8;i++)
        #pragma unroll
        for (int j=0;j<4;j++) acc[i][j] = 0ULL;

    #pragma unroll 8
    for (int kd = 0; kd < 128; kd++){
        const float4* xp = (const float4*)(xsT + kd*128 + m0);
        float4 a0 = xp[0], a1 = xp[1];
        const float4* wp = (const float4*)(Ws + kd*WROW + k0);
        float4 w0 = wp[0], w1 = wp[1];
        unsigned long long rw0 = pk2(w0.x,w0.y), rw1 = pk2(w0.z,w0.w);
        unsigned long long rw2 = pk2(w1.x,w1.y), rw3 = pk2(w1.z,w1.w);
        float xv[8] = {a0.x,a0.y,a0.z,a0.w,a1.x,a1.y,a1.z,a1.w};
        #pragma unroll
        for (int i=0;i<8;i++){
            unsigned long long xd = pk2(xv[i], xv[i]);
            fma2(acc[i][0], xd, rw0);
            fma2(acc[i][1], xd, rw1);
            fma2(acc[i][2], xd, rw2);
            fma2(acc[i][3], xd, rw3);
        }
    }

    // xsT no longer needed; zs reuses its storage
    __syncthreads();

    // ---- per-node: +bias, +gumbel, argmax over 8-lane group; stash z ----
    const float4* u4 = (const float4*)gu;
    #pragma unroll
    for (int i=0;i<8;i++){
        float z[8];
        #pragma unroll
        for (int j=0;j<4;j++){
            float lo, hi; unpk2(acc[i][j], lo, hi);
            z[2*j]   = add_rn(lo, bs[k0 + 2*j]);
            z[2*j+1] = add_rn(hi, bs[k0 + 2*j+1]);
        }
        int node = node0 + m0 + i;
        float4 u0 = u4[(size_t)node*16 + (k0>>2)];
        float4 u1 = u4[(size_t)node*16 + (k0>>2) + 1];
        float uu[8] = {u0.x,u0.y,u0.z,u0.w,u1.x,u1.y,u1.z,u1.w};
        #pragma unroll
        for (int j=0;j<8;j++){
            float g = -(logf)(-(logf)(uu[j]));   // accurate libdevice logf
            z[j] = add_rn(z[j], g);
        }

        // stash exact z for the bit-exact softmax-sum phase
        #pragma unroll
        for (int j=0;j<8;j++) zs[(m0+i)*ZROW + k0 + j] = z[j];

        // local argmax (first-max tie-break, like jnp.argmax)
        float mx = z[0]; int am = k0;
        #pragma unroll
        for (int j=1;j<8;j++) if (z[j] > mx){ mx = z[j]; am = k0+j; }
        // reduce across the 8 lanes holding this node's 64 logits
        #pragma unroll
        for (int off=1; off<8; off<<=1){
            float om = __shfl_xor_sync(0xffffffffu, mx, off);
            int   oa = __shfl_xor_sync(0xffffffffu, am, off);
            if (om > mx || (om == mx && oa < am)){ mx = om; am = oa; }
        }
        if (txk == 0){
            cs[m0+i]  = am;
            mxs[m0+i] = mx;
            atomicAdd(&g_counts[gb*64 + am], 1.0f);
        }
    }
    __syncthreads();
    g_c[node0 + t] = cs[t];

    // ---- phase 2: entropy; SEQUENTIAL ASCENDING softmax denominator ----
    {
        const int lane = t & 31;
        const float* zr = zs + t*ZROW;
        float m  = mxs[t];
        float se = (expf)(sub_rn(zr[0], m));
        #pragma unroll 8
        for (int j = 1; j < 64; j++)
            se = add_rn(se, (expf)(sub_rn(zr[j], m)));
        float ys = __fdiv_rn(1.0f, se);           // y_soft at the argmax
        float sh = sub_rn(add_rn(1.0f, ys), ys);  // straight-through fwd value
        float entloc = -sh * (logf)(sh + 1e-15f);
        #pragma unroll
        for (int off = 16; off; off >>= 1)
            entloc += __shfl_down_sync(0xffffffffu, entloc, off);
        if (lane == 0) atomicAdd(&g_ent, entloc);
    }
}

// ---------------------------------------------------------------------------
// K2: pooling, out[b,k,:] = sum of x rows with c==k.
// v2: 4-warp parallel list build. Each warp preloads its 1024 nodes' g_c into
// registers (MLP=32 -> one latency hit), ballots from registers, cross-warp
// prefix via smem, replays saved masks -> identical ascending list as v1.
// Gather loop unchanged -> byte-identical 'out'.
// ---------------------------------------------------------------------------
__global__ void __launch_bounds__(128)
k_pool(const float* __restrict__ x, float* __restrict__ dout)
{
    __shared__ int list[NPG];
    __shared__ int wcnt[4];
    const int blk = blockIdx.x;
    const int b = blk >> 6, k = blk & 63;
    const int base = b * NPG;
    const int t = threadIdx.x;
    const int lane = t & 31, w = t >> 5;

    // phase 1a: preload this warp's 1024 g_c values (independent loads)
    int cv[32];
    #pragma unroll
    for (int i = 0; i < 32; i++)
        cv[i] = g_c[base + w*1024 + i*32 + lane];

    // phase 1b: count matches, saving ballot masks
    unsigned masks[32];
    int cnt_w = 0;
    #pragma unroll
    for (int i = 0; i < 32; i++){
        unsigned m = __ballot_sync(0xffffffffu, cv[i] == k);
        masks[i] = m;
        cnt_w += __popc(m);
    }
    if (lane == 0) wcnt[w] = cnt_w;
    __syncthreads();

    // phase 1c: write ordered list at this warp's prefix offset
    int off = 0;
    #pragma unroll
    for (int i = 0; i < 4; i++) if (i < w) off += wcnt[i];
    #pragma unroll
    for (int i = 0; i < 32; i++){
        unsigned m = masks[i];
        if (cv[i] == k) list[off + __popc(m & ((1u<<lane)-1u))] = w*1024 + i*32 + lane;
        off += __popc(m);
    }
    __syncthreads();

    const int M = wcnt[0] + wcnt[1] + wcnt[2] + wcnt[3];
    float a0=0.f, a1=0.f, a2=0.f, a3=0.f;
    int idx = 0;
    for (; idx + 4 <= M; idx += 4){
        a0 += x[(size_t)(base + list[idx  ])*128 + t];
        a1 += x[(size_t)(base + list[idx+1])*128 + t];
        a2 += x[(size_t)(base + list[idx+2])*128 + t];
        a3 += x[(size_t)(base + list[idx+3])*128 + t];
    }
    for (; idx < M; idx++) a0 += x[(size_t)(base + list[idx])*128 + t];
    dout[(size_t)blk*128 + t] = (a0+a1)+(a2+a3);
}

// ---------------------------------------------------------------------------
// K3: edges -> out_adj via SMEM histogram. EPB=2048 -> 512 blocks (less wave
// tail, more latency overlap; R9: occ 43.5%, issue 12.8% at 256 blocks).
// ---------------------------------------------------------------------------
#define EPB 2048   // edges per block (32 blocks per graph)
#define ETH 512    // threads per block

__global__ void __launch_bounds__(ETH)
k_edges(const int* __restrict__ ei, const float* __restrict__ ew,
        float* __restrict__ adj)
{
    __shared__ float hist[KC*KC];       // 4096 floats = 16KB
    __shared__ float s_w2[ETH/32], s_cw[ETH/32];

    const int blk = blockIdx.x;         // 512 blocks
    const int b   = blk >> 5;           // graph id (32 blocks per graph)
    const int e0  = blk * EPB;
    const int t   = threadIdx.x;
    const int lane = t & 31, warp = t >> 5;

    // zero histogram: KC*KC/4 = 1024 float4 total, ETH threads
    float4* h4 = (float4*)hist;
    #pragma unroll
    for (int i = 0; i < KC*KC/4/ETH; i++)
        h4[i*ETH + t] = make_float4(0.f,0.f,0.f,0.f);
    __syncthreads();

    float w2 = 0.0f, cw = 0.0f;
    #pragma unroll
    for (int i = 0; i < EPB/ETH; i++){
        int e = e0 + i*ETH + t;
        int s = ei[e], d = ei[E_TOT + e];
        float w = ew[e];
        int cs_ = g_c[s], cd = g_c[d];   // L1-resident (16KB/graph window)
        atomicAdd(&hist[(cs_<<6) + cd], w);
        w2 += w*w;
        if (cs_ == cd) cw += w;
    }

    // block-reduce w2 / cw
    #pragma unroll
    for (int off=16; off; off>>=1){
        w2 += __shfl_down_sync(0xffffffffu, w2, off);
        cw += __shfl_down_sync(0xffffffffu, cw, off);
    }
    if (lane == 0){ s_w2[warp] = w2; s_cw[warp] = cw; }
    __syncthreads();
    if (t == 0){
        float tw2 = 0.f, tcw = 0.f;
        #pragma unroll
        for (int i=0;i<ETH/32;i++){ tw2 += s_w2[i]; tcw += s_cw[i]; }
        atomicAdd(&g_asq[b],   tw2);
        atomicAdd(&g_cross[b], tcw);
    }

    // merge histogram into adj (coalesced REDG; skip empty bins)
    float* adjb = adj + ((size_t)b << 12);
    #pragma unroll
    for (int i = 0; i < KC*KC/ETH; i++){
        int idx = i*ETH + t;
        float v = hist[idx];
        if (v != 0.0f) atomicAdd(&adjb[idx], v);
    }
}

// ---------------------------------------------------------------------------
// K4: link loss + entropy loss
// ---------------------------------------------------------------------------
__global__ void k_fin(float* __restrict__ dout){
    int t = threadIdx.x;  // 32 threads
    float link = 0.0f;
    if (t < NB){
        float sst = 0.0f;
        #pragma unroll
        for (int k=0;k<KC;k++){ float c = g_counts[t*KC+k]; sst += c*c; }
        float v = g_asq[t] - 2.0f*g_cross[t] + sst;
        link = sqrtf(fmaxf(v, 0.0f)) * (1.0f/65536.0f);   // / e_per
    }
    #pragma unroll
    for (int off=16; off; off>>=1) link += __shfl_down_sync(0xffffffffu, link, off);
    if (t == 0){
        dout[OFF_LINK] = link * (1.0f/16.0f);
        dout[OFF_ENT]  = g_ent * (1.0f/65536.0f);
    }
}

// ---------------------------------------------------------------------------
extern "C" void kernel_launch(void* const* d_in, const int* in_sizes, int n_in,
                              void* d_out, int out_size)
{
    const float* x  = (const float*)d_in[0];
    const float* W  = (const float*)d_in[1];
    const float* b  = (const float*)d_in[2];
    const float* ew = (const float*)d_in[3];
    const float* gu = (const float*)d_in[4];
    const int*   ei = (const int*)d_in[5];
    // d_in[6] = batch_ptr (int64) — graphs are equal-sized, unused
    float* dout = (float*)d_out;

    // xsT 16384 (zs aliased) + Ws 128*68 + bs 64 + mxs 128 floats + cs 128 ints
    const int smem = (16384 + 128*WROW + 64 + 128)*4 + 128*4;   // ~101.6KB
    cudaFuncSetAttribute(k_assign, cudaFuncAttributeMaxDynamicSharedMemorySize, smem);

    k_init  <<<777, 256>>>(dout);
    k_assign<<<NTOT/128, 128, smem>>>(x, W, b, gu);
    k_pool  <<<NB*KC, 128>>>(x, dout);
    k_edges <<<E_TOT/EPB, ETH>>>(ei, ew, dout + OFF_ADJ);
    k_fin   <<<1, 32>>>(dout);
}

// round 11
// speedup vs baseline: 2.0735x; 1.0822x over previous
#include <cuda_runtime.h>
#include <math.h>

#ifdef expf
#undef expf
#endif
#ifdef logf
#undef logf
#endif

#define E_TOT 1048576
#define NTOT  65536
#define NB    16
#define NPG   4096
#define KC    64
#define DD    128

// d_out layout (float32, flattened reference tuple)
#define OFF_ADJ   131072
#define OFF_LINK  196608
#define OFF_ENT   196609
#define OFF_BATCH 196610
#define OFF_PTR   197634
#define OUT_TOT   197651

// scratch (device globals — no allocation allowed)
__device__ int   g_c[NTOT];
__device__ float g_counts[NB*KC];
__device__ float g_cross[NB];
__device__ float g_asq[NB];
__device__ float g_ent;
__device__ int   g_done;

// ---------------------------------------------------------------------------
// packed f32x2 helpers (Blackwell FFMA2 — 2x fp32 throughput, PTX-only path)
// ---------------------------------------------------------------------------
__device__ __forceinline__ unsigned long long pk2(float lo, float hi){
    unsigned long long r;
    asm("mov.b64 %0, {%1, %2};" : "=l"(r) : "f"(lo), "f"(hi));
    return r;
}
__device__ __forceinline__ void fma2(unsigned long long& d, unsigned long long a, unsigned long long b){
    asm("fma.rn.f32x2 %0, %1, %2, %0;" : "+l"(d) : "l"(a), "l"(b));
}
__device__ __forceinline__ void unpk2(unsigned long long v, float& lo, float& hi){
    asm("mov.b64 {%0, %1}, %2;" : "=f"(lo), "=f"(hi) : "l"(v));
}
// IEEE add/sub the compiler cannot simplify or contract
__device__ __forceinline__ float add_rn(float a, float b){
    float r; asm("add.rn.f32 %0, %1, %2;" : "=f"(r) : "f"(a), "f"(b)); return r;
}
__device__ __forceinline__ float sub_rn(float a, float b){
    float r; asm("sub.rn.f32 %0, %1, %2;" : "=f"(r) : "f"(a), "f"(b)); return r;
}

// ---------------------------------------------------------------------------
// K0: zero accumulators + write constant outputs (batch, batch_ptr_out)
// ---------------------------------------------------------------------------
__global__ void k_init(float* __restrict__ dout){
    int i = blockIdx.x*256 + threadIdx.x;
    if (i < OFF_LINK) dout[i] = 0.0f;                                   // out + out_adj
    else if (i >= OFF_BATCH && i < OFF_PTR)  dout[i] = (float)((i-OFF_BATCH) >> 6);
    else if (i >= OFF_PTR   && i < OUT_TOT)  dout[i] = (float)((i-OFF_PTR) << 6);
    int j = i - OUT_TOT;
    if (j >= 0){
        if      (j < NB*KC)          g_counts[j] = 0.0f;
        else if (j < NB*KC+NB)       g_cross[j-NB*KC] = 0.0f;
        else if (j < NB*KC+2*NB)     g_asq[j-NB*KC-NB] = 0.0f;
        else if (j == NB*KC+2*NB)    g_ent = 0.0f;
        else if (j == NB*KC+2*NB+1)  g_done = 0;
    }
}

// ---------------------------------------------------------------------------
// K1: logits GEMM (fp32, f32x2-packed) + gumbel argmax + counts + entropy + c[]
// Per-thread FP DAGs frozen (passes at rel_err 9.3e-4).
// Split-kd GEMM: xsT holds 64 depth rows (32KB), staged twice, ascending-kd
// accumulation preserved -> bit-identical. smem ~69KB => 3 blocks/SM.
// zs aliases xsT + (dead) front of Ws after the GEMM barrier.
// ---------------------------------------------------------------------------
#define WROW 68   // padded smem row stride for W
#define ZROW 65   // padded smem row stride for zs (conflict-free: (t+j)%32 distinct)

// float offsets into dynamic smem
#define SM_XST 0            // [64 kd][128 n] = 8192 floats (GEMM phase)
#define SM_WS  8192         // [128][WROW] = 8704 floats
#define SM_ZS  0            // ALIAS [128 n][ZROW] = 8320 floats (epilogue)
#define SM_BS  16896        // [64]
#define SM_MXS 16960        // [128]
#define SM_CS  17088        // [128] ints
#define SM_TOT 17216        // floats => 68864 B

__global__ void __launch_bounds__(128, 3)
k_assign(const float* __restrict__ x, const float* __restrict__ W,
         const float* __restrict__ bias, const float* __restrict__ gu)
{
    extern __shared__ float sm[];
    float* xsT = sm + SM_XST;
    float* zs  = sm + SM_ZS;
    float* Ws  = sm + SM_WS;
    float* bs  = sm + SM_BS;
    float* mxs = sm + SM_MXS;
    int*   cs  = (int*)(sm + SM_CS);

    const int t     = threadIdx.x;
    const int node0 = blockIdx.x * 128;
    const int gb    = node0 >> 12;      // graph id (4096 nodes per graph)

    // ---- stage W [128,64] into padded smem (coalesced float4 loads) ----
    const float4* W4 = (const float4*)W;
    #pragma unroll
    for (int it = 0; it < 16; it++){
        int f = it*128 + t;             // 2048 float4 total
        float4 v = W4[f];
        int kd = f >> 4, kq = (f & 15) << 2;
        float* p = Ws + kd*WROW + kq;
        p[0]=v.x; p[1]=v.y; p[2]=v.z; p[3]=v.w;
    }
    if (t < 64) bs[t] = bias[t];

    const int txk = t & 7, tyn = t >> 3;
    const int k0 = txk << 3, m0 = tyn << 3;

    unsigned long long acc[8][4];
    #pragma unroll
    for (int i=0;i<8;i++)
        #pragma unroll
        for (int j=0;j<4;j++) acc[i][j] = 0ULL;

    const float4* x4 = (const float4*)x;

    // ---- two kd chunks of 64; ascending kd order preserved exactly ----
    #pragma unroll 1
    for (int c = 0; c < 2; c++){
        __syncthreads();   // xsT free (prev chunk consumed / W-stage done)
        #pragma unroll
        for (int it = 0; it < 16; it++){
            int f = it*128 + t;         // 2048 float4 per chunk
            int n = f & 127, dq = f >> 7;   // dq in [0,16)
            float4 v = x4[(size_t)(node0 + n)*32 + c*16 + dq];
            float* p = xsT + (dq*4)*128 + n;
            p[0]   = v.x; p[128] = v.y; p[256] = v.z; p[384] = v.w;
        }
        __syncthreads();

        const float* Wc = Ws + (c*64)*WROW;
        #pragma unroll 8
        for (int kd = 0; kd < 64; kd++){
            const float4* xp = (const float4*)(xsT + kd*128 + m0);
            float4 a0 = xp[0], a1 = xp[1];
            const float4* wp = (const float4*)(Wc + kd*WROW + k0);
            float4 w0 = wp[0], w1 = wp[1];
            unsigned long long rw0 = pk2(w0.x,w0.y), rw1 = pk2(w0.z,w0.w);
            unsigned long long rw2 = pk2(w1.x,w1.y), rw3 = pk2(w1.z,w1.w);
            float xv[8] = {a0.x,a0.y,a0.z,a0.w,a1.x,a1.y,a1.z,a1.w};
            #pragma unroll
            for (int i=0;i<8;i++){
                unsigned long long xd = pk2(xv[i], xv[i]);
                fma2(acc[i][0], xd, rw0);
                fma2(acc[i][1], xd, rw1);
                fma2(acc[i][2], xd, rw2);
                fma2(acc[i][3], xd, rw3);
            }
        }
    }

    // xsT (and front of Ws) no longer needed; zs reuses the storage
    __syncthreads();

    // ---- per-node: +bias, +gumbel, argmax over 8-lane group; stash z ----
    const float4* u4 = (const float4*)gu;
    #pragma unroll
    for (int i=0;i<8;i++){
        float z[8];
        #pragma unroll
        for (int j=0;j<4;j++){
            float lo, hi; unpk2(acc[i][j], lo, hi);
            z[2*j]   = add_rn(lo, bs[k0 + 2*j]);
            z[2*j+1] = add_rn(hi, bs[k0 + 2*j+1]);
        }
        int node = node0 + m0 + i;
        float4 u0 = u4[(size_t)node*16 + (k0>>2)];
        float4 u1 = u4[(size_t)node*16 + (k0>>2) + 1];
        float uu[8] = {u0.x,u0.y,u0.z,u0.w,u1.x,u1.y,u1.z,u1.w};
        #pragma unroll
        for (int j=0;j<8;j++){
            float g = -(logf)(-(logf)(uu[j]));   // accurate libdevice logf
            z[j] = add_rn(z[j], g);
        }

        // stash exact z for the bit-exact softmax-sum phase
        #pragma unroll
        for (int j=0;j<8;j++) zs[(m0+i)*ZROW + k0 + j] = z[j];

        // local argmax (first-max tie-break, like jnp.argmax)
        float mx = z[0]; int am = k0;
        #pragma unroll
        for (int j=1;j<8;j++) if (z[j] > mx){ mx = z[j]; am = k0+j; }
        // reduce across the 8 lanes holding this node's 64 logits
        #pragma unroll
        for (int off=1; off<8; off<<=1){
            float om = __shfl_xor_sync(0xffffffffu, mx, off);
            int   oa = __shfl_xor_sync(0xffffffffu, am, off);
            if (om > mx || (om == mx && oa < am)){ mx = om; am = oa; }
        }
        if (txk == 0){
            cs[m0+i]  = am;
            mxs[m0+i] = mx;
            atomicAdd(&g_counts[gb*64 + am], 1.0f);
        }
    }
    __syncthreads();
    g_c[node0 + t] = cs[t];

    // ---- phase 2: entropy; SEQUENTIAL ASCENDING softmax denominator ----
    {
        const int lane = t & 31;
        const float* zr = zs + t*ZROW;
        float m  = mxs[t];
        float se = (expf)(sub_rn(zr[0], m));
        #pragma unroll 8
        for (int j = 1; j < 64; j++)
            se = add_rn(se, (expf)(sub_rn(zr[j], m)));
        float ys = __fdiv_rn(1.0f, se);           // y_soft at the argmax
        float sh = sub_rn(add_rn(1.0f, ys), ys);  // straight-through fwd value
        float entloc = -sh * (logf)(sh + 1e-15f);
        #pragma unroll
        for (int off = 16; off; off >>= 1)
            entloc += __shfl_down_sync(0xffffffffu, entloc, off);
        if (lane == 0) atomicAdd(&g_ent, entloc);
    }
}

// ---------------------------------------------------------------------------
// K2: pooling, out[b,k,:] = sum of x rows with c==k (4-warp parallel list
// build; gather loop order identical -> byte-identical 'out')
// ---------------------------------------------------------------------------
__global__ void __launch_bounds__(128)
k_pool(const float* __restrict__ x, float* __restrict__ dout)
{
    __shared__ int list[NPG];
    __shared__ int wcnt[4];
    const int blk = blockIdx.x;
    const int b = blk >> 6, k = blk & 63;
    const int base = b * NPG;
    const int t = threadIdx.x;
    const int lane = t & 31, w = t >> 5;

    int cv[32];
    #pragma unroll
    for (int i = 0; i < 32; i++)
        cv[i] = g_c[base + w*1024 + i*32 + lane];

    unsigned masks[32];
    int cnt_w = 0;
    #pragma unroll
    for (int i = 0; i < 32; i++){
        unsigned m = __ballot_sync(0xffffffffu, cv[i] == k);
        masks[i] = m;
        cnt_w += __popc(m);
    }
    if (lane == 0) wcnt[w] = cnt_w;
    __syncthreads();

    int off = 0;
    #pragma unroll
    for (int i = 0; i < 4; i++) if (i < w) off += wcnt[i];
    #pragma unroll
    for (int i = 0; i < 32; i++){
        unsigned m = masks[i];
        if (cv[i] == k) list[off + __popc(m & ((1u<<lane)-1u))] = w*1024 + i*32 + lane;
        off += __popc(m);
    }
    __syncthreads();

    const int M = wcnt[0] + wcnt[1] + wcnt[2] + wcnt[3];
    float a0=0.f, a1=0.f, a2=0.f, a3=0.f;
    int idx = 0;
    for (; idx + 4 <= M; idx += 4){
        a0 += x[(size_t)(base + list[idx  ])*128 + t];
        a1 += x[(size_t)(base + list[idx+1])*128 + t];
        a2 += x[(size_t)(base + list[idx+2])*128 + t];
        a3 += x[(size_t)(base + list[idx+3])*128 + t];
    }
    for (; idx < M; idx++) a0 += x[(size_t)(base + list[idx])*128 + t];
    dout[(size_t)blk*128 + t] = (a0+a1)+(a2+a3);
}

// ---------------------------------------------------------------------------
// K3: edges -> out_adj via SMEM histogram; batched loads for MLP; the LAST
// block to finish also computes link/entropy losses (fenced counter).
// ---------------------------------------------------------------------------
#define EPB 2048   // edges per block (32 blocks per graph)
#define ETH 512    // threads per block
#define NBLK (E_TOT/EPB)

__global__ void __launch_bounds__(ETH)
k_edges(const int* __restrict__ ei, const float* __restrict__ ew,
        float* __restrict__ dout)
{
    __shared__ float hist[KC*KC];       // 4096 floats = 16KB
    __shared__ float s_w2[ETH/32], s_cw[ETH/32];
    __shared__ int   s_rank;

    float* adj = dout + OFF_ADJ;
    const int blk = blockIdx.x;         // 512 blocks
    const int b   = blk >> 5;           // graph id (32 blocks per graph)
    const int e0  = blk * EPB;
    const int t   = threadIdx.x;
    const int lane = t & 31, warp = t >> 5;

    // zero histogram
    float4* h4 = (float4*)hist;
    #pragma unroll
    for (int i = 0; i < KC*KC/4/ETH; i++)
        h4[i*ETH + t] = make_float4(0.f,0.f,0.f,0.f);
    __syncthreads();

    // batched loads (MLP), then gathers, then atomics; w2/cw order preserved
    int   sv[EPB/ETH], dv[EPB/ETH];
    float wv[EPB/ETH];
    #pragma unroll
    for (int i = 0; i < EPB/ETH; i++){
        int e = e0 + i*ETH + t;
        sv[i] = ei[e];
        dv[i] = ei[E_TOT + e];
        wv[i] = ew[e];
    }
    int c1[EPB/ETH], c2[EPB/ETH];
    #pragma unroll
    for (int i = 0; i < EPB/ETH; i++){
        c1[i] = g_c[sv[i]];
        c2[i] = g_c[dv[i]];
    }
    float w2 = 0.0f, cw = 0.0f;
    #pragma unroll
    for (int i = 0; i < EPB/ETH; i++){
        atomicAdd(&hist[(c1[i]<<6) + c2[i]], wv[i]);
        w2 += wv[i]*wv[i];
        if (c1[i] == c2[i]) cw += wv[i];
    }

    // block-reduce w2 / cw
    #pragma unroll
    for (int off=16; off; off>>=1){
        w2 += __shfl_down_sync(0xffffffffu, w2, off);
        cw += __shfl_down_sync(0xffffffffu, cw, off);
    }
    if (lane == 0){ s_w2[warp] = w2; s_cw[warp] = cw; }
    __syncthreads();
    if (t == 0){
        float tw2 = 0.f, tcw = 0.f;
        #pragma unroll
        for (int i=0;i<ETH/32;i++){ tw2 += s_w2[i]; tcw += s_cw[i]; }
        atomicAdd(&g_asq[b],   tw2);
        atomicAdd(&g_cross[b], tcw);
        __threadfence();
        s_rank = atomicAdd(&g_done, 1);
    }

    // merge histogram into adj (coalesced REDG; skip empty bins)
    #pragma unroll
    for (int i = 0; i < KC*KC/ETH; i++){
        int idx = i*ETH + t;
        float v = hist[idx];
        if (v != 0.0f) atomicAdd(&adj[((size_t)b << 12) + idx], v);
    }

    __syncthreads();
    // last block computes the losses (identical math to the old k_fin)
    if (s_rank == NBLK - 1 && t < 32){
        __threadfence();
        float link = 0.0f;
        if (t < NB){
            float sst = 0.0f;
            #pragma unroll
            for (int k=0;k<KC;k++){ float c = g_counts[t*KC+k]; sst += c*c; }
            float v = g_asq[t] - 2.0f*g_cross[t] + sst;
            link = sqrtf(fmaxf(v, 0.0f)) * (1.0f/65536.0f);   // / e_per
        }
        #pragma unroll
        for (int off=16; off; off>>=1) link += __shfl_down_sync(0xffffffffu, link, off);
        if (t == 0){
            dout[OFF_LINK] = link * (1.0f/16.0f);
            dout[OFF_ENT]  = g_ent * (1.0f/65536.0f);
        }
    }
}

// ---------------------------------------------------------------------------
extern "C" void kernel_launch(void* const* d_in, const int* in_sizes, int n_in,
                              void* d_out, int out_size)
{
    const float* x  = (const float*)d_in[0];
    const float* W  = (const float*)d_in[1];
    const float* b  = (const float*)d_in[2];
    const float* ew = (const float*)d_in[3];
    const float* gu = (const float*)d_in[4];
    const int*   ei = (const int*)d_in[5];
    // d_in[6] = batch_ptr (int64) — graphs are equal-sized, unused
    float* dout = (float*)d_out;

    const int smem = SM_TOT*4;   // 68864 B -> 3 blocks/SM
    cudaFuncSetAttribute(k_assign, cudaFuncAttributeMaxDynamicSharedMemorySize, smem);

    k_init  <<<777, 256>>>(dout);
    k_assign<<<NTOT/128, 128, smem>>>(x, W, b, gu);
    k_pool  <<<NB*KC, 128>>>(x, dout);
    k_edges <<<NBLK, ETH>>>(ei, ew, dout);
}

// round 12
// speedup vs baseline: 2.0792x; 1.0027x over previous
#include <cuda_runtime.h>
#include <math.h>

#ifdef expf
#undef expf
#endif
#ifdef logf
#undef logf
#endif

#define E_TOT 1048576
#define NTOT  65536
#define NB    16
#define NPG   4096
#define KC    64
#define DD    128

// d_out layout (float32, flattened reference tuple)
#define OFF_ADJ   131072
#define OFF_LINK  196608
#define OFF_ENT   196609
#define OFF_BATCH 196610
#define OFF_PTR   197634
#define OUT_TOT   197651

// scratch (device globals — no allocation allowed)
__device__ int   g_c[NTOT];
__device__ float g_counts[NB*KC];
__device__ float g_cross[NB];
__device__ float g_asq[NB];
__device__ float g_ent;
__device__ int   g_done;

// ---------------------------------------------------------------------------
// packed f32x2 helpers (Blackwell FFMA2 — 2x fp32 throughput, PTX-only path)
// ---------------------------------------------------------------------------
__device__ __forceinline__ unsigned long long pk2(float lo, float hi){
    unsigned long long r;
    asm("mov.b64 %0, {%1, %2};" : "=l"(r) : "f"(lo), "f"(hi));
    return r;
}
__device__ __forceinline__ void fma2(unsigned long long& d, unsigned long long a, unsigned long long b){
    asm("fma.rn.f32x2 %0, %1, %2, %0;" : "+l"(d) : "l"(a), "l"(b));
}
__device__ __forceinline__ void unpk2(unsigned long long v, float& lo, float& hi){
    asm("mov.b64 {%0, %1}, %2;" : "=f"(lo), "=f"(hi) : "l"(v));
}
// IEEE add/sub the compiler cannot simplify or contract
__device__ __forceinline__ float add_rn(float a, float b){
    float r; asm("add.rn.f32 %0, %1, %2;" : "=f"(r) : "f"(a), "f"(b)); return r;
}
__device__ __forceinline__ float sub_rn(float a, float b){
    float r; asm("sub.rn.f32 %0, %1, %2;" : "=f"(r) : "f"(a), "f"(b)); return r;
}

// ---------------------------------------------------------------------------
// K0: zero accumulators + write constant outputs (batch, batch_ptr_out)
// ---------------------------------------------------------------------------
__global__ void k_init(float* __restrict__ dout){
    int i = blockIdx.x*256 + threadIdx.x;
    if (i < OFF_LINK) dout[i] = 0.0f;                                   // out + out_adj
    else if (i >= OFF_BATCH && i < OFF_PTR)  dout[i] = (float)((i-OFF_BATCH) >> 6);
    else if (i >= OFF_PTR   && i < OUT_TOT)  dout[i] = (float)((i-OFF_PTR) << 6);
    int j = i - OUT_TOT;
    if (j >= 0){
        if      (j < NB*KC)          g_counts[j] = 0.0f;
        else if (j < NB*KC+NB)       g_cross[j-NB*KC] = 0.0f;
        else if (j < NB*KC+2*NB)     g_asq[j-NB*KC-NB] = 0.0f;
        else if (j == NB*KC+2*NB)    g_ent = 0.0f;
        else if (j == NB*KC+2*NB+1)  g_done = 0;
    }
}

// ---------------------------------------------------------------------------
// K1: logits GEMM (fp32, f32x2-packed) + gumbel argmax + counts + entropy + c[]
// Per-thread FP DAGs frozen (passes at rel_err 9.3e-4).
// Split-kd GEMM with per-chunk W staging: xsT [64][128] = 32KB, Ws [64][WROW]
// = 17.4KB -> smem ~50.3KB => 4 blocks/SM (16 warps). Ascending-kd order
// preserved -> bit-identical. zs aliases xsT + dead Ws after the GEMM.
// ---------------------------------------------------------------------------
#define WROW 68   // padded smem row stride for W
#define ZROW 65   // padded smem row stride for zs

// float offsets into dynamic smem
#define SM_XST 0            // [64 kd][128 n] = 8192 floats (GEMM phase)
#define SM_WS  8192         // [64][WROW] = 4352 floats (per-chunk W)
#define SM_ZS  0            // ALIAS [128 n][ZROW] = 8320 floats (epilogue)
#define SM_BS  12544        // [64]
#define SM_MXS 12608        // [128]
#define SM_CS  12736        // [128] ints
#define SM_TOT 12864        // floats => 51456 B

__global__ void __launch_bounds__(128, 4)
k_assign(const float* __restrict__ x, const float* __restrict__ W,
         const float* __restrict__ bias, const float* __restrict__ gu)
{
    extern __shared__ float sm[];
    float* xsT = sm + SM_XST;
    float* zs  = sm + SM_ZS;
    float* Ws  = sm + SM_WS;
    float* bs  = sm + SM_BS;
    float* mxs = sm + SM_MXS;
    int*   cs  = (int*)(sm + SM_CS);

    const int t     = threadIdx.x;
    const int node0 = blockIdx.x * 128;
    const int gb    = node0 >> 12;      // graph id (4096 nodes per graph)

    if (t < 64) bs[t] = bias[t];

    const int txk = t & 7, tyn = t >> 3;
    const int k0 = txk << 3, m0 = tyn << 3;

    unsigned long long acc[8][4];
    #pragma unroll
    for (int i=0;i<8;i++)
        #pragma unroll
        for (int j=0;j<4;j++) acc[i][j] = 0ULL;

    const float4* x4 = (const float4*)x;
    const float4* W4 = (const float4*)W;

    // ---- two kd chunks of 64; ascending kd order preserved exactly ----
    #pragma unroll 1
    for (int c = 0; c < 2; c++){
        __syncthreads();   // xsT/Ws free (prev chunk consumed)

        // stage W rows [c*64, c*64+64) : 1024 float4
        #pragma unroll
        for (int it = 0; it < 8; it++){
            int f = it*128 + t;
            float4 v = W4[c*1024 + f];
            int kd = f >> 4, kq = (f & 15) << 2;
            float* p = Ws + kd*WROW + kq;
            p[0]=v.x; p[1]=v.y; p[2]=v.z; p[3]=v.w;
        }
        // stage x tile transposed for this chunk: 2048 float4
        #pragma unroll
        for (int it = 0; it < 16; it++){
            int f = it*128 + t;
            int n = f & 127, dq = f >> 7;   // dq in [0,16)
            float4 v = x4[(size_t)(node0 + n)*32 + c*16 + dq];
            float* p = xsT + (dq*4)*128 + n;
            p[0]   = v.x; p[128] = v.y; p[256] = v.z; p[384] = v.w;
        }
        __syncthreads();

        #pragma unroll 8
        for (int kd = 0; kd < 64; kd++){
            const float4* xp = (const float4*)(xsT + kd*128 + m0);
            float4 a0 = xp[0], a1 = xp[1];
            const float4* wp = (const float4*)(Ws + kd*WROW + k0);
            float4 w0 = wp[0], w1 = wp[1];
            unsigned long long rw0 = pk2(w0.x,w0.y), rw1 = pk2(w0.z,w0.w);
            unsigned long long rw2 = pk2(w1.x,w1.y), rw3 = pk2(w1.z,w1.w);
            float xv[8] = {a0.x,a0.y,a0.z,a0.w,a1.x,a1.y,a1.z,a1.w};
            #pragma unroll
            for (int i=0;i<8;i++){
                unsigned long long xd = pk2(xv[i], xv[i]);
                fma2(acc[i][0], xd, rw0);
                fma2(acc[i][1], xd, rw1);
                fma2(acc[i][2], xd, rw2);
                fma2(acc[i][3], xd, rw3);
            }
        }
    }

    // xsT/Ws no longer needed; zs reuses the storage
    __syncthreads();

    // ---- per-node: +bias, +gumbel, argmax over 8-lane group; stash z ----
    const float4* u4 = (const float4*)gu;
    #pragma unroll
    for (int i=0;i<8;i++){
        float z[8];
        #pragma unroll
        for (int j=0;j<4;j++){
            float lo, hi; unpk2(acc[i][j], lo, hi);
            z[2*j]   = add_rn(lo, bs[k0 + 2*j]);
            z[2*j+1] = add_rn(hi, bs[k0 + 2*j+1]);
        }
        int node = node0 + m0 + i;
        float4 u0 = u4[(size_t)node*16 + (k0>>2)];
        float4 u1 = u4[(size_t)node*16 + (k0>>2) + 1];
        float uu[8] = {u0.x,u0.y,u0.z,u0.w,u1.x,u1.y,u1.z,u1.w};
        #pragma unroll
        for (int j=0;j<8;j++){
            float g = -(logf)(-(logf)(uu[j]));   // accurate libdevice logf
            z[j] = add_rn(z[j], g);
        }

        // stash exact z for the bit-exact softmax-sum phase
        #pragma unroll
        for (int j=0;j<8;j++) zs[(m0+i)*ZROW + k0 + j] = z[j];

        // local argmax (first-max tie-break, like jnp.argmax)
        float mx = z[0]; int am = k0;
        #pragma unroll
        for (int j=1;j<8;j++) if (z[j] > mx){ mx = z[j]; am = k0+j; }
        // reduce across the 8 lanes holding this node's 64 logits
        #pragma unroll
        for (int off=1; off<8; off<<=1){
            float om = __shfl_xor_sync(0xffffffffu, mx, off);
            int   oa = __shfl_xor_sync(0xffffffffu, am, off);
            if (om > mx || (om == mx && oa < am)){ mx = om; am = oa; }
        }
        if (txk == 0){
            cs[m0+i]  = am;
            mxs[m0+i] = mx;
            atomicAdd(&g_counts[gb*64 + am], 1.0f);
        }
    }
    __syncthreads();
    g_c[node0 + t] = cs[t];

    // ---- phase 2: entropy; SEQUENTIAL ASCENDING softmax denominator ----
    {
        const int lane = t & 31;
        const float* zr = zs + t*ZROW;
        float m  = mxs[t];
        float se = (expf)(sub_rn(zr[0], m));
        #pragma unroll 8
        for (int j = 1; j < 64; j++)
            se = add_rn(se, (expf)(sub_rn(zr[j], m)));
        float ys = __fdiv_rn(1.0f, se);           // y_soft at the argmax
        float sh = sub_rn(add_rn(1.0f, ys), ys);  // straight-through fwd value
        float entloc = -sh * (logf)(sh + 1e-15f);
        #pragma unroll
        for (int off = 16; off; off >>= 1)
            entloc += __shfl_down_sync(0xffffffffu, entloc, off);
        if (lane == 0) atomicAdd(&g_ent, entloc);
    }
}

// ---------------------------------------------------------------------------
// K2: pooling, out[b,k,:] = sum of x rows with c==k (4-warp parallel list
// build; gather loop order identical -> byte-identical 'out')
// ---------------------------------------------------------------------------
__global__ void __launch_bounds__(128)
k_pool(const float* __restrict__ x, float* __restrict__ dout)
{
    __shared__ int list[NPG];
    __shared__ int wcnt[4];
    const int blk = blockIdx.x;
    const int b = blk >> 6, k = blk & 63;
    const int base = b * NPG;
    const int t = threadIdx.x;
    const int lane = t & 31, w = t >> 5;

    int cv[32];
    #pragma unroll
    for (int i = 0; i < 32; i++)
        cv[i] = g_c[base + w*1024 + i*32 + lane];

    unsigned masks[32];
    int cnt_w = 0;
    #pragma unroll
    for (int i = 0; i < 32; i++){
        unsigned m = __ballot_sync(0xffffffffu, cv[i] == k);
        masks[i] = m;
        cnt_w += __popc(m);
    }
    if (lane == 0) wcnt[w] = cnt_w;
    __syncthreads();

    int off = 0;
    #pragma unroll
    for (int i = 0; i < 4; i++) if (i < w) off += wcnt[i];
    #pragma unroll
    for (int i = 0; i < 32; i++){
        unsigned m = masks[i];
        if (cv[i] == k) list[off + __popc(m & ((1u<<lane)-1u))] = w*1024 + i*32 + lane;
        off += __popc(m);
    }
    __syncthreads();

    const int M = wcnt[0] + wcnt[1] + wcnt[2] + wcnt[3];
    float a0=0.f, a1=0.f, a2=0.f, a3=0.f;
    int idx = 0;
    for (; idx + 4 <= M; idx += 4){
        a0 += x[(size_t)(base + list[idx  ])*128 + t];
        a1 += x[(size_t)(base + list[idx+1])*128 + t];
        a2 += x[(size_t)(base + list[idx+2])*128 + t];
        a3 += x[(size_t)(base + list[idx+3])*128 + t];
    }
    for (; idx < M; idx++) a0 += x[(size_t)(base + list[idx])*128 + t];
    dout[(size_t)blk*128 + t] = (a0+a1)+(a2+a3);
}

// ---------------------------------------------------------------------------
// K3: edges -> out_adj via SMEM histogram; INTERLEAVED per-edge loop (R10
// form — hand-batching regressed: ptxas pipelines the interleaved form
// better). Last block computes the losses (fenced counter).
// ---------------------------------------------------------------------------
#define EPB 2048   // edges per block (32 blocks per graph)
#define ETH 512    // threads per block
#define NBLK (E_TOT/EPB)

__global__ void __launch_bounds__(ETH)
k_edges(const int* __restrict__ ei, const float* __restrict__ ew,
        float* __restrict__ dout)
{
    __shared__ float hist[KC*KC];       // 4096 floats = 16KB
    __shared__ float s_w2[ETH/32], s_cw[ETH/32];
    __shared__ int   s_rank;

    float* adj = dout + OFF_ADJ;
    const int blk = blockIdx.x;         // 512 blocks
    const int b   = blk >> 5;           // graph id (32 blocks per graph)
    const int e0  = blk * EPB;
    const int t   = threadIdx.x;
    const int lane = t & 31, warp = t >> 5;

    // zero histogram
    float4* h4 = (float4*)hist;
    #pragma unroll
    for (int i = 0; i < KC*KC/4/ETH; i++)
        h4[i*ETH + t] = make_float4(0.f,0.f,0.f,0.f);
    __syncthreads();

    float w2 = 0.0f, cw = 0.0f;
    #pragma unroll
    for (int i = 0; i < EPB/ETH; i++){
        int e = e0 + i*ETH + t;
        int s = ei[e], d = ei[E_TOT + e];
        float w = ew[e];
        int cs_ = g_c[s], cd = g_c[d];   // L1-resident (16KB/graph window)
        atomicAdd(&hist[(cs_<<6) + cd], w);
        w2 += w*w;
        if (cs_ == cd) cw += w;
    }

    // block-reduce w2 / cw
    #pragma unroll
    for (int off=16; off; off>>=1){
        w2 += __shfl_down_sync(0xffffffffu, w2, off);
        cw += __shfl_down_sync(0xffffffffu, cw, off);
    }
    if (lane == 0){ s_w2[warp] = w2; s_cw[warp] = cw; }
    __syncthreads();
    if (t == 0){
        float tw2 = 0.f, tcw = 0.f;
        #pragma unroll
        for (int i=0;i<ETH/32;i++){ tw2 += s_w2[i]; tcw += s_cw[i]; }
        atomicAdd(&g_asq[b],   tw2);
        atomicAdd(&g_cross[b], tcw);
        __threadfence();
        s_rank = atomicAdd(&g_done, 1);
    }

    // merge histogram into adj (coalesced REDG; skip empty bins)
    #pragma unroll
    for (int i = 0; i < KC*KC/ETH; i++){
        int idx = i*ETH + t;
        float v = hist[idx];
        if (v != 0.0f) atomicAdd(&adj[((size_t)b << 12) + idx], v);
    }

    __syncthreads();
    // last block computes the losses (identical math to the old k_fin)
    if (s_rank == NBLK - 1 && t < 32){
        __threadfence();
        float link = 0.0f;
        if (t < NB){
            float sst = 0.0f;
            #pragma unroll
            for (int k=0;k<KC;k++){ float c = g_counts[t*KC+k]; sst += c*c; }
            float v = g_asq[t] - 2.0f*g_cross[t] + sst;
            link = sqrtf(fmaxf(v, 0.0f)) * (1.0f/65536.0f);   // / e_per
        }
        #pragma unroll
        for (int off=16; off; off>>=1) link += __shfl_down_sync(0xffffffffu, link, off);
        if (t == 0){
            dout[OFF_LINK] = link * (1.0f/16.0f);
            dout[OFF_ENT]  = g_ent * (1.0f/65536.0f);
        }
    }
}

// ---------------------------------------------------------------------------
extern "C" void kernel_launch(void* const* d_in, const int* in_sizes, int n_in,
                              void* d_out, int out_size)
{
    const float* x  = (const float*)d_in[0];
    const float* W  = (const float*)d_in[1];
    const float* b  = (const float*)d_in[2];
    const float* ew = (const float*)d_in[3];
    const float* gu = (const float*)d_in[4];
    const int*   ei = (const int*)d_in[5];
    // d_in[6] = batch_ptr (int64) — graphs are equal-sized, unused
    float* dout = (float*)d_out;

    const int smem = SM_TOT*4;   // 51456 B -> 4 blocks/SM
    cudaFuncSetAttribute(k_assign, cudaFuncAttributeMaxDynamicSharedMemorySize, smem);

    k_init  <<<777, 256>>>(dout);
    k_assign<<<NTOT/128, 128, smem>>>(x, W, b, gu);
    k_pool  <<<NB*KC, 128>>>(x, dout);
    k_edges <<<NBLK, ETH>>>(ei, ew, dout);
}

// round 13
// speedup vs baseline: 2.2818x; 1.0974x over previous
#include <cuda_runtime.h>
#include <math.h>

#ifdef expf
#undef expf
#endif
#ifdef logf
#undef logf
#endif

#define E_TOT 1048576
#define NTOT  65536
#define NB    16
#define NPG   4096
#define KC    64
#define DD    128

// d_out layout (float32, flattened reference tuple)
#define OFF_ADJ   131072
#define OFF_LINK  196608
#define OFF_ENT   196609
#define OFF_BATCH 196610
#define OFF_PTR   197634
#define OUT_TOT   197651

// scratch (device globals — no allocation allowed)
__device__ int   g_c[NTOT];
__device__ float g_counts[NB*KC];
__device__ float g_cross[NB];
__device__ float g_asq[NB];
__device__ float g_ent;

// ---------------------------------------------------------------------------
// packed f32x2 helpers (Blackwell FFMA2 — 2x fp32 throughput, PTX-only path)
// ---------------------------------------------------------------------------
__device__ __forceinline__ unsigned long long pk2(float lo, float hi){
    unsigned long long r;
    asm("mov.b64 %0, {%1, %2};" : "=l"(r) : "f"(lo), "f"(hi));
    return r;
}
__device__ __forceinline__ void fma2(unsigned long long& d, unsigned long long a, unsigned long long b){
    asm("fma.rn.f32x2 %0, %1, %2, %0;" : "+l"(d) : "l"(a), "l"(b));
}
__device__ __forceinline__ void unpk2(unsigned long long v, float& lo, float& hi){
    asm("mov.b64 {%0, %1}, %2;" : "=f"(lo), "=f"(hi) : "l"(v));
}
// IEEE add/sub the compiler cannot simplify or contract
__device__ __forceinline__ float add_rn(float a, float b){
    float r; asm("add.rn.f32 %0, %1, %2;" : "=f"(r) : "f"(a), "f"(b)); return r;
}
__device__ __forceinline__ float sub_rn(float a, float b){
    float r; asm("sub.rn.f32 %0, %1, %2;" : "=f"(r) : "f"(a), "f"(b)); return r;
}

// ---------------------------------------------------------------------------
// K0: zero adj + accumulators + constant outputs. 'out' region is NOT zeroed:
// k_pool fully overwrites all 131072 elements.
// ---------------------------------------------------------------------------
__global__ void k_init(float* __restrict__ dout){
    int i = OFF_ADJ + blockIdx.x*256 + threadIdx.x;
    if (i < OFF_LINK) dout[i] = 0.0f;                                   // out_adj
    else if (i >= OFF_BATCH && i < OFF_PTR)  dout[i] = (float)((i-OFF_BATCH) >> 6);
    else if (i >= OFF_PTR   && i < OUT_TOT)  dout[i] = (float)((i-OFF_PTR) << 6);
    int j = i - OUT_TOT;
    if (j >= 0){
        if      (j < NB*KC)        g_counts[j] = 0.0f;
        else if (j < NB*KC+NB)     g_cross[j-NB*KC] = 0.0f;
        else if (j < NB*KC+2*NB)   g_asq[j-NB*KC-NB] = 0.0f;
        else if (j == NB*KC+2*NB)  g_ent = 0.0f;
    }
}

// ---------------------------------------------------------------------------
// K1: logits GEMM (fp32, f32x2-packed) + gumbel argmax + counts + entropy + c[]
// Per-thread FP DAGs frozen (passes at rel_err 9.3474e-4).
// NEW data path (bit-identical math): x stored ROW-MAJOR in smem with a
// float4-group XOR swizzle (q' = q ^ ((n>>3)&3)). Staging LDG is fully
// coalesced (was 32-line uncoalesced in the transposed scheme — ~7.5us of
// L1tex wavefront time). GEMM loops g(4-kd float4 group) outer, r inner:
// kd = c*64 + 4g + r strictly ascending -> identical accumulation chains.
// ---------------------------------------------------------------------------
#define WROW 68   // padded smem row stride for W (17 float4)
#define ZROW 65   // padded smem row stride for zs

// float offsets into dynamic smem
#define SM_XS  0            // [128 n][16 f4] = 8192 floats (row-major, swizzled)
#define SM_WS  8192         // [64][WROW] = 4352 floats (per-chunk W)
#define SM_ZS  0            // ALIAS [128 n][ZROW] = 8320 floats (epilogue)
#define SM_BS  12544        // [64]
#define SM_MXS 12608        // [128]
#define SM_CS  12736        // [128] ints
#define SM_TOT 12864        // floats => 51456 B

__global__ void __launch_bounds__(128, 4)
k_assign(const float* __restrict__ x, const float* __restrict__ W,
         const float* __restrict__ bias, const float* __restrict__ gu)
{
    extern __shared__ float sm[];
    float4* xs4 = (float4*)(sm + SM_XS);
    float*  zs  = sm + SM_ZS;
    float*  Ws  = sm + SM_WS;
    float*  bs  = sm + SM_BS;
    float*  mxs = sm + SM_MXS;
    int*    cs  = (int*)(sm + SM_CS);

    const int t     = threadIdx.x;
    const int node0 = blockIdx.x * 128;
    const int gb    = node0 >> 12;      // graph id (4096 nodes per graph)

    if (t < 64) bs[t] = bias[t];

    const int txk = t & 7, tyn = t >> 3;
    const int k0 = txk << 3, m0 = tyn << 3;
    const int swz = tyn & 3;            // x swizzle for this thread's nodes

    unsigned long long acc[8][4];
    #pragma unroll
    for (int i=0;i<8;i++)
        #pragma unroll
        for (int j=0;j<4;j++) acc[i][j] = 0ULL;

    const float4* x4 = (const float4*)x;
    const float4* W4 = (const float4*)W;
    const float4* Ws4 = (const float4*)Ws;

    // ---- two kd chunks of 64; ascending kd order preserved exactly ----
    #pragma unroll 1
    for (int c = 0; c < 2; c++){
        __syncthreads();   // xs/Ws free (prev chunk consumed)

        // stage W rows [c*64, c*64+64) : 1024 float4
        #pragma unroll
        for (int it = 0; it < 8; it++){
            int f = it*128 + t;
            float4 v = W4[c*1024 + f];
            int kd = f >> 4, kq = (f & 15) << 2;
            float* p = Ws + kd*WROW + kq;
            p[0]=v.x; p[1]=v.y; p[2]=v.z; p[3]=v.w;
        }
        // stage x row-major, swizzled: COALESCED LDG (256B per node)
        #pragma unroll
        for (int it = 0; it < 16; it++){
            int f = it*128 + t;
            int n = f >> 4, q = f & 15;
            float4 v = x4[(size_t)(node0 + n)*32 + c*16 + q];
            xs4[n*16 + (q ^ ((n>>3)&3))] = v;
        }
        __syncthreads();

        #pragma unroll 4
        for (int g = 0; g < 16; g++){
            // this thread's 8 node-float4s for kd group g (conflict-free)
            float4 xv[8];
            #pragma unroll
            for (int i=0;i<8;i++)
                xv[i] = xs4[(m0+i)*16 + (g ^ swz)];
            #pragma unroll
            for (int r = 0; r < 4; r++){         // kd = c*64 + 4g + r, ascending
                const float4* wp = Ws4 + (4*g + r)*17 + 2*txk;
                float4 w0 = wp[0], w1 = wp[1];
                unsigned long long rw0 = pk2(w0.x,w0.y), rw1 = pk2(w0.z,w0.w);
                unsigned long long rw2 = pk2(w1.x,w1.y), rw3 = pk2(w1.z,w1.w);
                #pragma unroll
                for (int i=0;i<8;i++){
                    float xr = (r==0) ? xv[i].x : (r==1) ? xv[i].y :
                               (r==2) ? xv[i].z : xv[i].w;
                    unsigned long long xd = pk2(xr, xr);
                    fma2(acc[i][0], xd, rw0);
                    fma2(acc[i][1], xd, rw1);
                    fma2(acc[i][2], xd, rw2);
                    fma2(acc[i][3], xd, rw3);
                }
            }
        }
    }

    // xs/Ws no longer needed; zs reuses the storage
    __syncthreads();

    // ---- per-node: +bias, +gumbel, argmax over 8-lane group; stash z ----
    const float4* u4 = (const float4*)gu;
    #pragma unroll
    for (int i=0;i<8;i++){
        float z[8];
        #pragma unroll
        for (int j=0;j<4;j++){
            float lo, hi; unpk2(acc[i][j], lo, hi);
            z[2*j]   = add_rn(lo, bs[k0 + 2*j]);
            z[2*j+1] = add_rn(hi, bs[k0 + 2*j+1]);
        }
        int node = node0 + m0 + i;
        float4 u0 = u4[(size_t)node*16 + (k0>>2)];
        float4 u1 = u4[(size_t)node*16 + (k0>>2) + 1];
        float uu[8] = {u0.x,u0.y,u0.z,u0.w,u1.x,u1.y,u1.z,u1.w};
        #pragma unroll
        for (int j=0;j<8;j++){
            float g = -(logf)(-(logf)(uu[j]));   // accurate libdevice logf
            z[j] = add_rn(z[j], g);
        }

        // stash exact z for the bit-exact softmax-sum phase
        #pragma unroll
        for (int j=0;j<8;j++) zs[(m0+i)*ZROW + k0 + j] = z[j];

        // local argmax (first-max tie-break, like jnp.argmax)
        float mx = z[0]; int am = k0;
        #pragma unroll
        for (int j=1;j<8;j++) if (z[j] > mx){ mx = z[j]; am = k0+j; }
        // reduce across the 8 lanes holding this node's 64 logits
        #pragma unroll
        for (int off=1; off<8; off<<=1){
            float om = __shfl_xor_sync(0xffffffffu, mx, off);
            int   oa = __shfl_xor_sync(0xffffffffu, am, off);
            if (om > mx || (om == mx && oa < am)){ mx = om; am = oa; }
        }
        if (txk == 0){
            cs[m0+i]  = am;
            mxs[m0+i] = mx;
            atomicAdd(&g_counts[gb*64 + am], 1.0f);
        }
    }
    __syncthreads();
    g_c[node0 + t] = cs[t];

    // ---- phase 2: entropy; SEQUENTIAL ASCENDING softmax denominator ----
    {
        const int lane = t & 31;
        const float* zr = zs + t*ZROW;
        float m  = mxs[t];
        float se = (expf)(sub_rn(zr[0], m));
        #pragma unroll 8
        for (int j = 1; j < 64; j++)
            se = add_rn(se, (expf)(sub_rn(zr[j], m)));
        float ys = __fdiv_rn(1.0f, se);           // y_soft at the argmax
        float sh = sub_rn(add_rn(1.0f, ys), ys);  // straight-through fwd value
        float entloc = -sh * (logf)(sh + 1e-15f);
        #pragma unroll
        for (int off = 16; off; off >>= 1)
            entloc += __shfl_down_sync(0xffffffffu, entloc, off);
        if (lane == 0) atomicAdd(&g_ent, entloc);
    }
}

// ---------------------------------------------------------------------------
// K2: pooling, out[b,k,:] = sum of x rows with c==k (4-warp parallel list
// build; gather loop order identical -> byte-identical 'out')
// ---------------------------------------------------------------------------
__global__ void __launch_bounds__(128)
k_pool(const float* __restrict__ x, float* __restrict__ dout)
{
    __shared__ int list[NPG];
    __shared__ int wcnt[4];
    const int blk = blockIdx.x;
    const int b = blk >> 6, k = blk & 63;
    const int base = b * NPG;
    const int t = threadIdx.x;
    const int lane = t & 31, w = t >> 5;

    int cv[32];
    #pragma unroll
    for (int i = 0; i < 32; i++)
        cv[i] = g_c[base + w*1024 + i*32 + lane];

    unsigned masks[32];
    int cnt_w = 0;
    #pragma unroll
    for (int i = 0; i < 32; i++){
        unsigned m = __ballot_sync(0xffffffffu, cv[i] == k);
        masks[i] = m;
        cnt_w += __popc(m);
    }
    if (lane == 0) wcnt[w] = cnt_w;
    __syncthreads();

    int off = 0;
    #pragma unroll
    for (int i = 0; i < 4; i++) if (i < w) off += wcnt[i];
    #pragma unroll
    for (int i = 0; i < 32; i++){
        unsigned m = masks[i];
        if (cv[i] == k) list[off + __popc(m & ((1u<<lane)-1u))] = w*1024 + i*32 + lane;
        off += __popc(m);
    }
    __syncthreads();

    const int M = wcnt[0] + wcnt[1] + wcnt[2] + wcnt[3];
    float a0=0.f, a1=0.f, a2=0.f, a3=0.f;
    int idx = 0;
    for (; idx + 4 <= M; idx += 4){
        a0 += x[(size_t)(base + list[idx  ])*128 + t];
        a1 += x[(size_t)(base + list[idx+1])*128 + t];
        a2 += x[(size_t)(base + list[idx+2])*128 + t];
        a3 += x[(size_t)(base + list[idx+3])*128 + t];
    }
    for (; idx < M; idx++) a0 += x[(size_t)(base + list[idx])*128 + t];
    dout[(size_t)blk*128 + t] = (a0+a1)+(a2+a3);
}

// ---------------------------------------------------------------------------
// K3: edges -> out_adj via SMEM histogram (R10 proven form: interleaved loop,
// no fences/completion counter).
// ---------------------------------------------------------------------------
#define EPB 2048   // edges per block (32 blocks per graph)
#define ETH 512    // threads per block

__global__ void __launch_bounds__(ETH)
k_edges(const int* __restrict__ ei, const float* __restrict__ ew,
        float* __restrict__ adj)
{
    __shared__ float hist[KC*KC];       // 4096 floats = 16KB
    __shared__ float s_w2[ETH/32], s_cw[ETH/32];

    const int blk = blockIdx.x;         // 512 blocks
    const int b   = blk >> 5;           // graph id (32 blocks per graph)
    const int e0  = blk * EPB;
    const int t   = threadIdx.x;
    const int lane = t & 31, warp = t >> 5;

    // zero histogram
    float4* h4 = (float4*)hist;
    #pragma unroll
    for (int i = 0; i < KC*KC/4/ETH; i++)
        h4[i*ETH + t] = make_float4(0.f,0.f,0.f,0.f);
    __syncthreads();

    float w2 = 0.0f, cw = 0.0f;
    #pragma unroll
    for (int i = 0; i < EPB/ETH; i++){
        int e = e0 + i*ETH + t;
        int s = ei[e], d = ei[E_TOT + e];
        float w = ew[e];
        int cs_ = g_c[s], cd = g_c[d];   // L1-resident (16KB/graph window)
        atomicAdd(&hist[(cs_<<6) + cd], w);
        w2 += w*w;
        if (cs_ == cd) cw += w;
    }

    // block-reduce w2 / cw
    #pragma unroll
    for (int off=16; off; off>>=1){
        w2 += __shfl_down_sync(0xffffffffu, w2, off);
        cw += __shfl_down_sync(0xffffffffu, cw, off);
    }
    if (lane == 0){ s_w2[warp] = w2; s_cw[warp] = cw; }
    __syncthreads();
    if (t == 0){
        float tw2 = 0.f, tcw = 0.f;
        #pragma unroll
        for (int i=0;i<ETH/32;i++){ tw2 += s_w2[i]; tcw += s_cw[i]; }
        atomicAdd(&g_asq[b],   tw2);
        atomicAdd(&g_cross[b], tcw);
    }

    // merge histogram into adj (coalesced REDG; skip empty bins)
    float* adjb = adj + ((size_t)b << 12);
    #pragma unroll
    for (int i = 0; i < KC*KC/ETH; i++){
        int idx = i*ETH + t;
        float v = hist[idx];
        if (v != 0.0f) atomicAdd(&adjb[idx], v);
    }
}

// ---------------------------------------------------------------------------
// K4: link loss + entropy loss
// ---------------------------------------------------------------------------
__global__ void k_fin(float* __restrict__ dout){
    int t = threadIdx.x;  // 32 threads
    float link = 0.0f;
    if (t < NB){
        float sst = 0.0f;
        #pragma unroll
        for (int k=0;k<KC;k++){ float c = g_counts[t*KC+k]; sst += c*c; }
        float v = g_asq[t] - 2.0f*g_cross[t] + sst;
        link = sqrtf(fmaxf(v, 0.0f)) * (1.0f/65536.0f);   // / e_per
    }
    #pragma unroll
    for (int off=16; off; off>>=1) link += __shfl_down_sync(0xffffffffu, link, off);
    if (t == 0){
        dout[OFF_LINK] = link * (1.0f/16.0f);
        dout[OFF_ENT]  = g_ent * (1.0f/65536.0f);
    }
}

// ---------------------------------------------------------------------------
extern "C" void kernel_launch(void* const* d_in, const int* in_sizes, int n_in,
                              void* d_out, int out_size)
{
    const float* x  = (const float*)d_in[0];
    const float* W  = (const float*)d_in[1];
    const float* b  = (const float*)d_in[2];
    const float* ew = (const float*)d_in[3];
    const float* gu = (const float*)d_in[4];
    const int*   ei = (const int*)d_in[5];
    // d_in[6] = batch_ptr (int64) — graphs are equal-sized, unused
    float* dout = (float*)d_out;

    const int smem = SM_TOT*4;   // 51456 B -> 4 blocks/SM
    cudaFuncSetAttribute(k_assign, cudaFuncAttributeMaxDynamicSharedMemorySize, smem);

    k_init  <<<265, 256>>>(dout);
    k_assign<<<NTOT/128, 128, smem>>>(x, W, b, gu);
    k_pool  <<<NB*KC, 128>>>(x, dout);
    k_edges <<<E_TOT/EPB, ETH>>>(ei, ew, dout + OFF_ADJ);
    k_fin   <<<1, 32>>>(dout);
}